// round 10
// baseline (speedup 1.0000x reference)
#include <cuda_runtime.h>
#include <cuda_fp16.h>
#include <cuda_fp8.h>
#include <cstdint>

#define N_NODES 100000
#define N_EDGES 1600000
#define FNODE   32
#define FGLOB   16
#define HDIM    64
#define OUTDIM  64

#define MSG_SCALE     64.0f
#define INV_MSG_SCALE (1.0f / 64.0f)

#define SCAN_BS 1024
#define N_SCAN_BLOCKS ((N_NODES + SCAN_BS - 1) / SCAN_BS)   // 98

// ---------------- scratch (device globals: no allocations allowed) ----------
__device__ int   g_cnt[N_NODES];
__device__ int   g_rowoff[N_NODES];          // scan1: block-local excl; after fill: local END
__device__ int   g_bsum[N_SCAN_BLOCKS];      // exclusive block offsets
__device__ __align__(16) int g_csr[N_EDGES];
__device__ float g_dis[N_NODES];
__device__ __align__(16) unsigned int g_hw8a[(size_t)N_NODES * 16];  // fp8x4 msgs, 64B/row
__device__ __align__(16) unsigned int g_hw8b[(size_t)N_NODES * 16];
__device__ float g_pool[HDIM];

// ---------------- degree count over dst ----------------------------------------
__global__ void k_count(const int* __restrict__ dst) {
    int e = blockIdx.x * blockDim.x + threadIdx.x;
    if (e < N_EDGES) atomicAdd(&g_cnt[dst[e]], 1);
}

// ---------------- scan stage 1 (shuffle-based) + dis ----------------------------
__global__ void k_scan1() {
    __shared__ int wsum[32];
    int tid = threadIdx.x;
    int i = blockIdx.x * SCAN_BS + tid;
    int v = (i < N_NODES) ? g_cnt[i] : 0;
    if (i < N_NODES) g_dis[i] = rsqrtf((float)(v + 1));

    int lane = tid & 31, w = tid >> 5;
    int s = v;
    #pragma unroll
    for (int o = 1; o < 32; o <<= 1) {
        int t = __shfl_up_sync(0xffffffffu, s, o);
        if (lane >= o) s += t;
    }
    if (lane == 31) wsum[w] = s;
    __syncthreads();
    if (w == 0) {
        int ws = wsum[lane];
        int t = ws;
        #pragma unroll
        for (int o = 1; o < 32; o <<= 1) {
            int u = __shfl_up_sync(0xffffffffu, t, o);
            if (lane >= o) t += u;
        }
        wsum[lane] = t - ws;
        if (lane == 31) g_bsum[blockIdx.x] = t;
    }
    __syncthreads();
    if (i < N_NODES) g_rowoff[i] = wsum[w] + s - v;
}

// ---------------- scan stage 2 (+ pool zero) -------------------------------------
__global__ void k_scan2() {
    __shared__ int wsum[4];
    int tid = threadIdx.x;                 // 128 threads
    if (tid < HDIM) g_pool[tid] = 0.f;
    int v = (tid < N_SCAN_BLOCKS) ? g_bsum[tid] : 0;
    int lane = tid & 31, w = tid >> 5;
    int s = v;
    #pragma unroll
    for (int o = 1; o < 32; o <<= 1) {
        int t = __shfl_up_sync(0xffffffffu, s, o);
        if (lane >= o) s += t;
    }
    if (lane == 31) wsum[w] = s;
    __syncthreads();
    int woff = 0;
    #pragma unroll
    for (int k = 0; k < 4; k++) if (k < w) woff += wsum[k];
    if (tid < N_SCAN_BLOCKS) g_bsum[tid] = woff + s - v;
}

// ---------------- CSR fill: single fetch-and-add on rowoff + bsum add ------------
__global__ void k_fill(const int* __restrict__ src, const int* __restrict__ dst) {
    int e = blockIdx.x * blockDim.x + threadIdx.x;
    if (e < N_EDGES) {
        int d = dst[e];
        int pos = atomicAdd(&g_rowoff[d], 1) + g_bsum[d >> 10];
        g_csr[pos] = src[e];
    }
}

// ---------------- fp8x2 -> half2 helpers -----------------------------------------
__device__ __forceinline__ __half2 fp8x2_to_h2(unsigned short u) {
    __half2_raw hr = __nv_cvt_fp8x2_to_halfraw2(u, __NV_E4M3);
    return *reinterpret_cast<__half2*>(&hr);
}
__device__ __forceinline__ __half2 u2h2(unsigned int u) {
    return *reinterpret_cast<__half2*>(&u);
}

#define APITCH 72      // halves; conflict-free ldmatrix
#define S8P    36      // ushorts per padded fp8 row (32 data + 4 pad)

// ---------------- layer-1: fused embed + HMMA -> hw8 -----------------------------
__global__ void k_hmma1(const float* __restrict__ w,
                        const float* __restrict__ xin, const float* __restrict__ wn,
                        const float* __restrict__ bn,
                        unsigned int* __restrict__ out8) {
    __shared__ __half Wsm[HDIM * APITCH];
    __shared__ __half Asm[128 * APITCH];
    __shared__ float WnS[FNODE * HDIM];
    __shared__ float BnS[HDIM];
    int tid = threadIdx.x;
    int lane = tid & 31, wid = tid >> 5;
    int rowBase = blockIdx.x * 128;

    for (int i = tid; i < HDIM * HDIM; i += 256) {
        int r = i >> 6, c = i & 63;
        Wsm[r * APITCH + c] = __float2half(w[i]);
    }
    for (int i = tid; i < FNODE * HDIM / 4; i += 256)
        reinterpret_cast<float4*>(WnS)[i] = reinterpret_cast<const float4*>(wn)[i];
    if (tid < HDIM) BnS[tid] = bn[tid];
    __syncthreads();

    // embed: row = tid>>1, colBase = (tid&1)*32; acc over K=32
    {
        int row = tid >> 1;
        int colBase = (tid & 1) * 32;
        int gr = rowBase + row;
        float acc[32];
        #pragma unroll
        for (int c = 0; c < 32; c++) acc[c] = 0.f;
        if (gr < N_NODES) {
            const float4* xr = reinterpret_cast<const float4*>(xin + (size_t)gr * FNODE);
            #pragma unroll
            for (int k4 = 0; k4 < FNODE / 4; ++k4) {
                float4 a = __ldg(&xr[k4]);
                const float av[4] = {a.x, a.y, a.z, a.w};
                #pragma unroll
                for (int kk = 0; kk < 4; ++kk) {
                    const float4* wrow = reinterpret_cast<const float4*>(
                        &WnS[(k4 * 4 + kk) * HDIM + colBase]);
                    float xa = av[kk];
                    #pragma unroll
                    for (int c4 = 0; c4 < 8; c4++) {
                        float4 wv = wrow[c4];
                        acc[c4*4+0] += xa * wv.x;
                        acc[c4*4+1] += xa * wv.y;
                        acc[c4*4+2] += xa * wv.z;
                        acc[c4*4+3] += xa * wv.w;
                    }
                }
            }
        }
        #pragma unroll
        for (int c2 = 0; c2 < 16; c2++) {
            __half2 hv = __floats2half2_rn(acc[2*c2]   + BnS[colBase + 2*c2],
                                           acc[2*c2+1] + BnS[colBase + 2*c2 + 1]);
            *reinterpret_cast<__half2*>(&Asm[row * APITCH + colBase + 2*c2]) = hv;
        }
    }
    __syncthreads();

    float acc[8][4];
    #pragma unroll
    for (int j = 0; j < 8; j++)
        #pragma unroll
        for (int q = 0; q < 4; q++) acc[j][q] = 0.f;

    uint32_t aAddr = (uint32_t)__cvta_generic_to_shared(
        &Asm[(wid * 16 + (lane & 15)) * APITCH + (lane >> 4) * 8]);
    uint32_t bAddr = (uint32_t)__cvta_generic_to_shared(
        &Wsm[(lane & 15) * APITCH]);

    #pragma unroll
    for (int k = 0; k < 4; k++) {
        uint32_t a0, a1, a2, a3;
        asm volatile("ldmatrix.sync.aligned.m8n8.x4.shared.b16 {%0,%1,%2,%3}, [%4];\n"
                     : "=r"(a0), "=r"(a1), "=r"(a2), "=r"(a3)
                     : "r"(aAddr + k * 16 * 2));
        #pragma unroll
        for (int j = 0; j < 8; j++) {
            uint32_t b0, b1;
            asm volatile("ldmatrix.sync.aligned.m8n8.x2.trans.shared.b16 {%0,%1}, [%2];\n"
                         : "=r"(b0), "=r"(b1)
                         : "r"(bAddr + (k * 16 * APITCH + j * 8) * 2));
            asm volatile("mma.sync.aligned.m16n8k16.row.col.f32.f16.f16.f32 "
                         "{%0,%1,%2,%3}, {%4,%5,%6,%7}, {%8,%9}, {%0,%1,%2,%3};\n"
                         : "+f"(acc[j][0]), "+f"(acc[j][1]), "+f"(acc[j][2]), "+f"(acc[j][3])
                         : "r"(a0), "r"(a1), "r"(a2), "r"(a3), "r"(b0), "r"(b1));
        }
    }

    __syncthreads();
    unsigned short* S8 = reinterpret_cast<unsigned short*>(Asm);   // [128][S8P]

    int g = lane >> 2, q = lane & 3;
    int r0l = wid * 16 + g;
    int r1l = r0l + 8;
    int gr0 = rowBase + r0l, gr1 = rowBase + r1l;
    float d0 = (gr0 < N_NODES) ? g_dis[gr0] * MSG_SCALE : 0.f;
    float d1 = (gr1 < N_NODES) ? g_dis[gr1] * MSG_SCALE : 0.f;
    #pragma unroll
    for (int j = 0; j < 8; j++) {
        S8[r0l * S8P + j * 4 + q] = __nv_cvt_float2_to_fp8x2(
            make_float2(acc[j][0] * d0, acc[j][1] * d0), __NV_SATFINITE, __NV_E4M3);
        S8[r1l * S8P + j * 4 + q] = __nv_cvt_float2_to_fp8x2(
            make_float2(acc[j][2] * d1, acc[j][3] * d1), __NV_SATFINITE, __NV_E4M3);
    }
    __syncthreads();

    for (int i = tid; i < 128 * 8; i += 256) {
        int r = i >> 3, c = i & 7;
        int grow = rowBase + r;
        if (grow < N_NODES) {
            uint2 v = *reinterpret_cast<const uint2*>(&S8[r * S8P + c * 4]);
            *reinterpret_cast<uint2*>(&out8[(size_t)grow * 16 + c * 2]) = v;
        }
    }
}

// ---------------- fused: agg(128 nodes) -> [HMMA -> hw8_out | pool] --------------
// agg: warp per node, 16 nodes per warp; 8 lanes/row, 4 edges per LDG.
// POOL=false: aggregated h rows go into the MMA A-tile (SMEM), MMA with w, fp8 out.
// POOL=true : fp32 relu'd h values are block-reduced and atomically added to g_pool.
template<bool POOL>
__global__ void k_fused(const uint2* __restrict__ hw_in, const float* __restrict__ bias,
                        const float* __restrict__ w, unsigned int* __restrict__ out8) {
    __shared__ __half Wsm[POOL ? 1 : HDIM * APITCH];
    __shared__ __half Asm[POOL ? 1 : 128 * APITCH];
    __shared__ float  Psm[POOL ? 8 * HDIM : 1];
    int tid = threadIdx.x;
    int lane = tid & 31, wid = tid >> 5;
    int rowBase = blockIdx.x * 128;
    int e = lane >> 3, s = lane & 7;

    if (!POOL) {
        for (int i = tid; i < HDIM * HDIM; i += 256) {
            int r = i >> 6, c = i & 63;
            Wsm[r * APITCH + c] = __float2half(w[i]);
        }
    }

    float4 bA = __ldg(reinterpret_cast<const float4*>(bias) + 2 * s);
    float4 bB = __ldg(reinterpret_cast<const float4*>(bias) + 2 * s + 1);

    float poolacc[8];
    if (POOL) {
        #pragma unroll
        for (int i = 0; i < 8; i++) poolacc[i] = 0.f;
    }

    // ---- aggregation phase: warp wid handles rows {k*8+wid}, k=0..15 ----
    for (int k = 0; k < 16; k++) {
        int row = k * 8 + wid;
        int node = rowBase + row;
        if (node < N_NODES) {      // warp-uniform
            __half2 acc0 = __float2half2_rn(0.f), acc1 = acc0, acc2 = acc0, acc3 = acc0;
            if (e == 0) {          // self loop
                uint2 v = __ldg(&hw_in[(size_t)node * 8 + s]);
                acc0 = fp8x2_to_h2((unsigned short)(v.x & 0xffffu));
                acc1 = fp8x2_to_h2((unsigned short)(v.x >> 16));
                acc2 = fp8x2_to_h2((unsigned short)(v.y & 0xffffu));
                acc3 = fp8x2_to_h2((unsigned short)(v.y >> 16));
            }
            int endl = g_rowoff[node] + g_bsum[node >> 10];   // after fill: row end
            int beg  = endl - g_cnt[node];
            int j = beg;
            for (; j + 4 <= endl; j += 4) {
                int idx = __ldg(&g_csr[j + e]);
                uint2 v = __ldg(&hw_in[(size_t)idx * 8 + s]);
                acc0 = __hadd2(acc0, fp8x2_to_h2((unsigned short)(v.x & 0xffffu)));
                acc1 = __hadd2(acc1, fp8x2_to_h2((unsigned short)(v.x >> 16)));
                acc2 = __hadd2(acc2, fp8x2_to_h2((unsigned short)(v.y & 0xffffu)));
                acc3 = __hadd2(acc3, fp8x2_to_h2((unsigned short)(v.y >> 16)));
            }
            int rem = endl - j;     // 0..3, warp-uniform
            if (e < rem) {
                int idx = __ldg(&g_csr[j + e]);
                uint2 v = __ldg(&hw_in[(size_t)idx * 8 + s]);
                acc0 = __hadd2(acc0, fp8x2_to_h2((unsigned short)(v.x & 0xffffu)));
                acc1 = __hadd2(acc1, fp8x2_to_h2((unsigned short)(v.x >> 16)));
                acc2 = __hadd2(acc2, fp8x2_to_h2((unsigned short)(v.y & 0xffffu)));
                acc3 = __hadd2(acc3, fp8x2_to_h2((unsigned short)(v.y >> 16)));
            }
            // reduce across edge slots (xor 8, 16)
            unsigned ua0 = *reinterpret_cast<unsigned*>(&acc0);
            unsigned ua1 = *reinterpret_cast<unsigned*>(&acc1);
            unsigned ua2 = *reinterpret_cast<unsigned*>(&acc2);
            unsigned ua3 = *reinterpret_cast<unsigned*>(&acc3);
            acc0 = __hadd2(u2h2(ua0), u2h2(__shfl_xor_sync(0xffffffffu, ua0, 8)));
            acc1 = __hadd2(u2h2(ua1), u2h2(__shfl_xor_sync(0xffffffffu, ua1, 8)));
            acc2 = __hadd2(u2h2(ua2), u2h2(__shfl_xor_sync(0xffffffffu, ua2, 8)));
            acc3 = __hadd2(u2h2(ua3), u2h2(__shfl_xor_sync(0xffffffffu, ua3, 8)));
            ua0 = *reinterpret_cast<unsigned*>(&acc0);
            ua1 = *reinterpret_cast<unsigned*>(&acc1);
            ua2 = *reinterpret_cast<unsigned*>(&acc2);
            ua3 = *reinterpret_cast<unsigned*>(&acc3);
            acc0 = __hadd2(u2h2(ua0), u2h2(__shfl_xor_sync(0xffffffffu, ua0, 16)));
            acc1 = __hadd2(u2h2(ua1), u2h2(__shfl_xor_sync(0xffffffffu, ua1, 16)));
            acc2 = __hadd2(u2h2(ua2), u2h2(__shfl_xor_sync(0xffffffffu, ua2, 16)));
            acc3 = __hadd2(u2h2(ua3), u2h2(__shfl_xor_sync(0xffffffffu, ua3, 16)));

            if (e == 0) {
                float di = g_dis[node] * INV_MSG_SCALE;
                float2 f0 = __half22float2(acc0), f1 = __half22float2(acc1);
                float2 f2 = __half22float2(acc2), f3 = __half22float2(acc3);
                float o0 = fmaxf(fmaf(di, f0.x, bA.x), 0.f);
                float o1 = fmaxf(fmaf(di, f0.y, bA.y), 0.f);
                float o2 = fmaxf(fmaf(di, f1.x, bA.z), 0.f);
                float o3 = fmaxf(fmaf(di, f1.y, bA.w), 0.f);
                float o4 = fmaxf(fmaf(di, f2.x, bB.x), 0.f);
                float o5 = fmaxf(fmaf(di, f2.y, bB.y), 0.f);
                float o6 = fmaxf(fmaf(di, f3.x, bB.z), 0.f);
                float o7 = fmaxf(fmaf(di, f3.y, bB.w), 0.f);
                if (POOL) {
                    poolacc[0] += o0; poolacc[1] += o1; poolacc[2] += o2; poolacc[3] += o3;
                    poolacc[4] += o4; poolacc[5] += o5; poolacc[6] += o6; poolacc[7] += o7;
                } else {
                    __half2 h0 = __floats2half2_rn(o0, o1);
                    __half2 h1 = __floats2half2_rn(o2, o3);
                    __half2 h2 = __floats2half2_rn(o4, o5);
                    __half2 h3 = __floats2half2_rn(o6, o7);
                    uint4 st;
                    st.x = *reinterpret_cast<unsigned*>(&h0);
                    st.y = *reinterpret_cast<unsigned*>(&h1);
                    st.z = *reinterpret_cast<unsigned*>(&h2);
                    st.w = *reinterpret_cast<unsigned*>(&h3);
                    *reinterpret_cast<uint4*>(&Asm[row * APITCH + s * 8]) = st;
                }
            }
        }
    }

    if (POOL) {
        if (e == 0) {
            #pragma unroll
            for (int i = 0; i < 8; i++) Psm[wid * HDIM + s * 8 + i] = poolacc[i];
        }
        __syncthreads();
        if (tid < HDIM) {
            float sum = 0.f;
            #pragma unroll
            for (int wv = 0; wv < 8; wv++) sum += Psm[wv * HDIM + tid];
            atomicAdd(&g_pool[tid], sum);
        }
        return;
    }

    __syncthreads();

    float acc[8][4];
    #pragma unroll
    for (int j = 0; j < 8; j++)
        #pragma unroll
        for (int q = 0; q < 4; q++) acc[j][q] = 0.f;

    uint32_t aAddr = (uint32_t)__cvta_generic_to_shared(
        &Asm[(wid * 16 + (lane & 15)) * APITCH + (lane >> 4) * 8]);
    uint32_t bAddr = (uint32_t)__cvta_generic_to_shared(
        &Wsm[(lane & 15) * APITCH]);

    #pragma unroll
    for (int k = 0; k < 4; k++) {
        uint32_t a0, a1, a2, a3;
        asm volatile("ldmatrix.sync.aligned.m8n8.x4.shared.b16 {%0,%1,%2,%3}, [%4];\n"
                     : "=r"(a0), "=r"(a1), "=r"(a2), "=r"(a3)
                     : "r"(aAddr + k * 16 * 2));
        #pragma unroll
        for (int j = 0; j < 8; j++) {
            uint32_t b0, b1;
            asm volatile("ldmatrix.sync.aligned.m8n8.x2.trans.shared.b16 {%0,%1}, [%2];\n"
                         : "=r"(b0), "=r"(b1)
                         : "r"(bAddr + (k * 16 * APITCH + j * 8) * 2));
            asm volatile("mma.sync.aligned.m16n8k16.row.col.f32.f16.f16.f32 "
                         "{%0,%1,%2,%3}, {%4,%5,%6,%7}, {%8,%9}, {%0,%1,%2,%3};\n"
                         : "+f"(acc[j][0]), "+f"(acc[j][1]), "+f"(acc[j][2]), "+f"(acc[j][3])
                         : "r"(a0), "r"(a1), "r"(a2), "r"(a3), "r"(b0), "r"(b1));
        }
    }

    __syncthreads();
    unsigned short* S8 = reinterpret_cast<unsigned short*>(Asm);   // [128][S8P]

    int g = lane >> 2, q = lane & 3;
    int r0l = wid * 16 + g;
    int r1l = r0l + 8;
    int gr0 = rowBase + r0l, gr1 = rowBase + r1l;
    float d0 = (gr0 < N_NODES) ? g_dis[gr0] * MSG_SCALE : 0.f;
    float d1 = (gr1 < N_NODES) ? g_dis[gr1] * MSG_SCALE : 0.f;
    #pragma unroll
    for (int j = 0; j < 8; j++) {
        S8[r0l * S8P + j * 4 + q] = __nv_cvt_float2_to_fp8x2(
            make_float2(acc[j][0] * d0, acc[j][1] * d0), __NV_SATFINITE, __NV_E4M3);
        S8[r1l * S8P + j * 4 + q] = __nv_cvt_float2_to_fp8x2(
            make_float2(acc[j][2] * d1, acc[j][3] * d1), __NV_SATFINITE, __NV_E4M3);
    }
    __syncthreads();

    for (int i = tid; i < 128 * 8; i += 256) {
        int r = i >> 3, c = i & 7;
        int grow = rowBase + r;
        if (grow < N_NODES) {
            uint2 v = *reinterpret_cast<const uint2*>(&S8[r * S8P + c * 4]);
            *reinterpret_cast<uint2*>(&out8[(size_t)grow * 16 + c * 2]) = v;
        }
    }
}

// ---------------- head ------------------------------------------------------------
__global__ void k_head(const float* __restrict__ gf,
                       const float* __restrict__ w_glob, const float* __restrict__ b_glob,
                       const float* __restrict__ w_fc1, const float* __restrict__ b_fc1,
                       const float* __restrict__ w_fc2, const float* __restrict__ b_fc2,
                       float* __restrict__ out) {
    __shared__ float xc[2 * HDIM];
    __shared__ float t1[HDIM];
    int t = threadIdx.x;

    xc[t] = g_pool[t] * (1.0f / (float)N_NODES);

    float a = b_glob[t];
    #pragma unroll
    for (int k = 0; k < FGLOB; k++) a += gf[k] * w_glob[k * HDIM + t];
    xc[HDIM + t] = fmaxf(a, 0.f);
    __syncthreads();

    float u = b_fc1[t];
    #pragma unroll 8
    for (int k = 0; k < 2 * HDIM; k++) u += xc[k] * w_fc1[k * HDIM + t];
    t1[t] = fmaxf(u, 0.f);
    __syncthreads();

    float o = b_fc2[t];
    #pragma unroll 8
    for (int k = 0; k < HDIM; k++) o += t1[k] * w_fc2[k * OUTDIM + t];
    out[t] = o;
}

// ---------------- launch ------------------------------------------------------
extern "C" void kernel_launch(void* const* d_in, const int* in_sizes, int n_in,
                              void* d_out, int out_size) {
    const float* x      = (const float*)d_in[0];
    const int*   ei     = (const int*)  d_in[1];   // [2,E]: first E = src, next E = dst
    const float* gf     = (const float*)d_in[2];
    const float* w_node = (const float*)d_in[3];
    const float* b_node = (const float*)d_in[4];
    const float* w_glob = (const float*)d_in[5];
    const float* b_glob = (const float*)d_in[6];
    const float* w_c[3] = {(const float*)d_in[7], (const float*)d_in[9],  (const float*)d_in[11]};
    const float* b_c[3] = {(const float*)d_in[8], (const float*)d_in[10], (const float*)d_in[12]};
    const float* w_fc1  = (const float*)d_in[13];
    const float* b_fc1  = (const float*)d_in[14];
    const float* w_fc2  = (const float*)d_in[15];
    const float* b_fc2  = (const float*)d_in[16];
    float* out = (float*)d_out;

    unsigned int *p_a, *p_b;
    int *p_cnt;
    cudaGetSymbolAddress((void**)&p_a,   g_hw8a);
    cudaGetSymbolAddress((void**)&p_b,   g_hw8b);
    cudaGetSymbolAddress((void**)&p_cnt, g_cnt);

    static cudaStream_t s_side = nullptr;
    static cudaEvent_t  s_evFork = nullptr, s_evDis = nullptr, s_evFill = nullptr;
    if (!s_side) {
        cudaStreamCreateWithFlags(&s_side, cudaStreamNonBlocking);
        cudaEventCreateWithFlags(&s_evFork, cudaEventDisableTiming);
        cudaEventCreateWithFlags(&s_evDis,  cudaEventDisableTiming);
        cudaEventCreateWithFlags(&s_evFill, cudaEventDisableTiming);
    }

    const int TB = 256;
    const int HG = (N_NODES + 127) / 128;   // 782 blocks

    // fork: CSR build chain on side stream
    cudaEventRecord(s_evFork, 0);
    cudaStreamWaitEvent(s_side, s_evFork, 0);
    cudaMemsetAsync(p_cnt, 0, N_NODES * sizeof(int), s_side);
    k_count<<<(N_EDGES + TB - 1) / TB, TB, 0, s_side>>>(ei + N_EDGES);
    k_scan1<<<N_SCAN_BLOCKS, SCAN_BS, 0, s_side>>>();           // writes dis
    cudaEventRecord(s_evDis, s_side);
    k_scan2<<<1, 128, 0, s_side>>>();                           // + pool zero
    k_fill <<<(N_EDGES + TB - 1) / TB, TB, 0, s_side>>>(ei, ei + N_EDGES);
    cudaEventRecord(s_evFill, s_side);

    // layer 1: fused embed + transform (needs dis for the epilogue)
    cudaStreamWaitEvent(0, s_evDis, 0);
    k_hmma1<<<HG, 256>>>(w_c[0], x, w_node, b_node, p_a);

    // layers 2,3: fused agg + transform (need CSR)
    cudaStreamWaitEvent(0, s_evFill, 0);
    k_fused<false><<<HG, 256>>>((const uint2*)p_a, b_c[0], w_c[1], p_b);
    k_fused<false><<<HG, 256>>>((const uint2*)p_b, b_c[1], w_c[2], p_a);
    // layer 3 aggregation fused with mean pool
    k_fused<true ><<<HG, 256>>>((const uint2*)p_a, b_c[2], nullptr, nullptr);

    k_head<<<1, 64>>>(gf, w_glob, b_glob, w_fc1, b_fc1, w_fc2, b_fc2, out);
}

// round 11
// speedup vs baseline: 1.0235x; 1.0235x over previous
#include <cuda_runtime.h>
#include <cuda_fp16.h>
#include <cuda_fp8.h>
#include <cstdint>

#define N_NODES 100000
#define N_EDGES 1600000
#define FNODE   32
#define FGLOB   16
#define HDIM    64
#define OUTDIM  64

#define MSG_SCALE     64.0f
#define INV_MSG_SCALE (1.0f / 64.0f)

#define SCAN_BS 1024
#define N_SCAN_BLOCKS ((N_NODES + SCAN_BS - 1) / SCAN_BS)   // 98

// ---------------- scratch (device globals: no allocations allowed) ----------
__device__ int   g_cnt[N_NODES];
__device__ int   g_rowoff[N_NODES];          // scan1: block-local excl; after fill: local END
__device__ int   g_bsum[N_SCAN_BLOCKS];      // exclusive block offsets
__device__ __align__(16) int g_csr[N_EDGES];
__device__ float g_dis[N_NODES];
__device__ __align__(16) __half g_hf[(size_t)N_NODES * HDIM];        // node features fp16
__device__ __align__(16) unsigned int g_hw8[(size_t)N_NODES * 16];   // fp8x4 msgs, 64B/row
__device__ float g_pool[HDIM];

// ---------------- degree count over dst (4 edges/thread) -------------------------
__global__ void k_count(const int4* __restrict__ dst4) {
    int t = blockIdx.x * blockDim.x + threadIdx.x;
    if (t < N_EDGES / 4) {
        int4 d = __ldg(&dst4[t]);
        atomicAdd(&g_cnt[d.x], 1);
        atomicAdd(&g_cnt[d.y], 1);
        atomicAdd(&g_cnt[d.z], 1);
        atomicAdd(&g_cnt[d.w], 1);
    }
}

// ---------------- scan stage 1 (shuffle-based) + dis ----------------------------
__global__ void k_scan1() {
    __shared__ int wsum[32];
    int tid = threadIdx.x;
    int i = blockIdx.x * SCAN_BS + tid;
    int v = (i < N_NODES) ? g_cnt[i] : 0;
    if (i < N_NODES) g_dis[i] = rsqrtf((float)(v + 1));

    int lane = tid & 31, w = tid >> 5;
    int s = v;
    #pragma unroll
    for (int o = 1; o < 32; o <<= 1) {
        int t = __shfl_up_sync(0xffffffffu, s, o);
        if (lane >= o) s += t;
    }
    if (lane == 31) wsum[w] = s;
    __syncthreads();
    if (w == 0) {
        int ws = wsum[lane];
        int t = ws;
        #pragma unroll
        for (int o = 1; o < 32; o <<= 1) {
            int u = __shfl_up_sync(0xffffffffu, t, o);
            if (lane >= o) t += u;
        }
        wsum[lane] = t - ws;
        if (lane == 31) g_bsum[blockIdx.x] = t;
    }
    __syncthreads();
    if (i < N_NODES) g_rowoff[i] = wsum[w] + s - v;
}

// ---------------- scan stage 2 (+ pool zero) -------------------------------------
__global__ void k_scan2() {
    __shared__ int wsum[4];
    int tid = threadIdx.x;                 // 128 threads
    if (tid < HDIM) g_pool[tid] = 0.f;
    int v = (tid < N_SCAN_BLOCKS) ? g_bsum[tid] : 0;
    int lane = tid & 31, w = tid >> 5;
    int s = v;
    #pragma unroll
    for (int o = 1; o < 32; o <<= 1) {
        int t = __shfl_up_sync(0xffffffffu, s, o);
        if (lane >= o) s += t;
    }
    if (lane == 31) wsum[w] = s;
    __syncthreads();
    int woff = 0;
    #pragma unroll
    for (int k = 0; k < 4; k++) if (k < w) woff += wsum[k];
    if (tid < N_SCAN_BLOCKS) g_bsum[tid] = woff + s - v;
}

// ---------------- CSR fill (4 edges/thread, single fetch-and-add) ----------------
__global__ void k_fill(const int4* __restrict__ src4, const int4* __restrict__ dst4) {
    int t = blockIdx.x * blockDim.x + threadIdx.x;
    if (t < N_EDGES / 4) {
        int4 sv = __ldg(&src4[t]);
        int4 dv = __ldg(&dst4[t]);
        int p0 = atomicAdd(&g_rowoff[dv.x], 1) + g_bsum[dv.x >> 10];
        g_csr[p0] = sv.x;
        int p1 = atomicAdd(&g_rowoff[dv.y], 1) + g_bsum[dv.y >> 10];
        g_csr[p1] = sv.y;
        int p2 = atomicAdd(&g_rowoff[dv.z], 1) + g_bsum[dv.z >> 10];
        g_csr[p2] = sv.z;
        int p3 = atomicAdd(&g_rowoff[dv.w], 1) + g_bsum[dv.w >> 10];
        g_csr[p3] = sv.w;
    }
}

// ---------------- fp8x2 -> half2 helpers -----------------------------------------
__device__ __forceinline__ __half2 fp8x2_to_h2(unsigned short u) {
    __half2_raw hr = __nv_cvt_fp8x2_to_halfraw2(u, __NV_E4M3);
    return *reinterpret_cast<__half2*>(&hr);
}
__device__ __forceinline__ __half2 u2h2(unsigned int u) {
    return *reinterpret_cast<__half2*>(&u);
}

#define APITCH 72      // halves; conflict-free ldmatrix
#define S8P    36      // ushorts per padded fp8 row (32 data + 4 pad)

// ---------------- HMMA conv transform: hw8 = fp8(64 * dis .* (A @ W)) ------------
// Block: 256 threads = 8 warps, 128 rows. EMBED: A = fp16(x @ Wn + bn) in-block.
template<bool EMBED>
__global__ void k_hmma(const __half* __restrict__ hin, const float* __restrict__ w,
                       const float* __restrict__ xin, const float* __restrict__ wn,
                       const float* __restrict__ bn,
                       unsigned int* __restrict__ out8) {
    __shared__ __half Wsm[HDIM * APITCH];
    __shared__ __half Asm[128 * APITCH];
    __shared__ float WnS[EMBED ? FNODE * HDIM : 1];
    __shared__ float BnS[EMBED ? HDIM : 1];
    int tid = threadIdx.x;
    int lane = tid & 31, wid = tid >> 5;
    int rowBase = blockIdx.x * 128;

    for (int i = tid; i < HDIM * HDIM; i += 256) {
        int r = i >> 6, c = i & 63;
        Wsm[r * APITCH + c] = __float2half(w[i]);
    }

    if (EMBED) {
        for (int i = tid; i < FNODE * HDIM / 4; i += 256)
            reinterpret_cast<float4*>(WnS)[i] = reinterpret_cast<const float4*>(wn)[i];
        if (tid < HDIM) BnS[tid] = bn[tid];
        __syncthreads();

        int row = tid >> 1;
        int colBase = (tid & 1) * 32;
        int gr = rowBase + row;
        float acc[32];
        #pragma unroll
        for (int c = 0; c < 32; c++) acc[c] = 0.f;
        if (gr < N_NODES) {
            const float4* xr = reinterpret_cast<const float4*>(xin + (size_t)gr * FNODE);
            #pragma unroll
            for (int k4 = 0; k4 < FNODE / 4; ++k4) {
                float4 a = __ldg(&xr[k4]);
                const float av[4] = {a.x, a.y, a.z, a.w};
                #pragma unroll
                for (int kk = 0; kk < 4; ++kk) {
                    const float4* wrow = reinterpret_cast<const float4*>(
                        &WnS[(k4 * 4 + kk) * HDIM + colBase]);
                    float xa = av[kk];
                    #pragma unroll
                    for (int c4 = 0; c4 < 8; c4++) {
                        float4 wv = wrow[c4];
                        acc[c4*4+0] += xa * wv.x;
                        acc[c4*4+1] += xa * wv.y;
                        acc[c4*4+2] += xa * wv.z;
                        acc[c4*4+3] += xa * wv.w;
                    }
                }
            }
        }
        #pragma unroll
        for (int c2 = 0; c2 < 16; c2++) {
            __half2 hv = __floats2half2_rn(acc[2*c2]   + BnS[colBase + 2*c2],
                                           acc[2*c2+1] + BnS[colBase + 2*c2 + 1]);
            *reinterpret_cast<__half2*>(&Asm[row * APITCH + colBase + 2*c2]) = hv;
        }
    } else {
        for (int i = tid; i < 128 * 16; i += 256) {
            int r = i >> 4, c4 = i & 15;
            int gr = rowBase + r;
            uint2 v = make_uint2(0u, 0u);
            if (gr < N_NODES)
                v = *reinterpret_cast<const uint2*>(hin + (size_t)gr * HDIM + c4 * 4);
            *reinterpret_cast<uint2*>(&Asm[r * APITCH + c4 * 4]) = v;
        }
    }
    __syncthreads();

    float acc[8][4];
    #pragma unroll
    for (int j = 0; j < 8; j++)
        #pragma unroll
        for (int q = 0; q < 4; q++) acc[j][q] = 0.f;

    uint32_t aAddr = (uint32_t)__cvta_generic_to_shared(
        &Asm[(wid * 16 + (lane & 15)) * APITCH + (lane >> 4) * 8]);
    uint32_t bAddr = (uint32_t)__cvta_generic_to_shared(
        &Wsm[(lane & 15) * APITCH]);

    #pragma unroll
    for (int k = 0; k < 4; k++) {
        uint32_t a0, a1, a2, a3;
        asm volatile("ldmatrix.sync.aligned.m8n8.x4.shared.b16 {%0,%1,%2,%3}, [%4];\n"
                     : "=r"(a0), "=r"(a1), "=r"(a2), "=r"(a3)
                     : "r"(aAddr + k * 16 * 2));
        #pragma unroll
        for (int j = 0; j < 8; j++) {
            uint32_t b0, b1;
            asm volatile("ldmatrix.sync.aligned.m8n8.x2.trans.shared.b16 {%0,%1}, [%2];\n"
                         : "=r"(b0), "=r"(b1)
                         : "r"(bAddr + (k * 16 * APITCH + j * 8) * 2));
            asm volatile("mma.sync.aligned.m16n8k16.row.col.f32.f16.f16.f32 "
                         "{%0,%1,%2,%3}, {%4,%5,%6,%7}, {%8,%9}, {%0,%1,%2,%3};\n"
                         : "+f"(acc[j][0]), "+f"(acc[j][1]), "+f"(acc[j][2]), "+f"(acc[j][3])
                         : "r"(a0), "r"(a1), "r"(a2), "r"(a3), "r"(b0), "r"(b1));
        }
    }

    __syncthreads();
    unsigned short* S8 = reinterpret_cast<unsigned short*>(Asm);   // [128][S8P]

    int g = lane >> 2, q = lane & 3;
    int r0l = wid * 16 + g;
    int r1l = r0l + 8;
    int gr0 = rowBase + r0l, gr1 = rowBase + r1l;
    float d0 = (gr0 < N_NODES) ? g_dis[gr0] * MSG_SCALE : 0.f;
    float d1 = (gr1 < N_NODES) ? g_dis[gr1] * MSG_SCALE : 0.f;
    #pragma unroll
    for (int j = 0; j < 8; j++) {
        S8[r0l * S8P + j * 4 + q] = __nv_cvt_float2_to_fp8x2(
            make_float2(acc[j][0] * d0, acc[j][1] * d0), __NV_SATFINITE, __NV_E4M3);
        S8[r1l * S8P + j * 4 + q] = __nv_cvt_float2_to_fp8x2(
            make_float2(acc[j][2] * d1, acc[j][3] * d1), __NV_SATFINITE, __NV_E4M3);
    }
    __syncthreads();

    for (int i = tid; i < 128 * 8; i += 256) {
        int r = i >> 3, c = i & 7;
        int grow = rowBase + r;
        if (grow < N_NODES) {
            uint2 v = *reinterpret_cast<const uint2*>(&S8[r * S8P + c * 4]);
            *reinterpret_cast<uint2*>(&out8[(size_t)grow * 16 + c * 2]) = v;
        }
    }
}

// ---------------- aggregation: warp/node, 8 lanes/row, 4 edges per LDG ----------
// POOL=false: write fp16 h rows. POOL=true: block-reduce relu'd h into g_pool.
template<bool POOL>
__global__ void k_agg(const uint2* __restrict__ hw,
                      const float* __restrict__ bias, __half* __restrict__ outh) {
    __shared__ float Psm[POOL ? 8 * HDIM : 1];
    int wid = threadIdx.x >> 5;
    int gw = (blockIdx.x * blockDim.x + threadIdx.x) >> 5;
    int lane = threadIdx.x & 31;
    int e = lane >> 3;           // edge slot 0..3
    int s = lane & 7;            // uint2 column (8 fp8 cols)
    bool valid = (gw < N_NODES);

    __half2 acc0 = __float2half2_rn(0.f), acc1 = acc0, acc2 = acc0, acc3 = acc0;

    if (valid) {
        if (e == 0) {            // self loop
            uint2 v = __ldg(&hw[(size_t)gw * 8 + s]);
            acc0 = fp8x2_to_h2((unsigned short)(v.x & 0xffffu));
            acc1 = fp8x2_to_h2((unsigned short)(v.x >> 16));
            acc2 = fp8x2_to_h2((unsigned short)(v.y & 0xffffu));
            acc3 = fp8x2_to_h2((unsigned short)(v.y >> 16));
        }
        int end = g_rowoff[gw] + g_bsum[gw >> 10];   // after fill: row end
        int beg = end - g_cnt[gw];
        int j = beg;
        for (; j + 4 <= end; j += 4) {
            int idx = __ldg(&g_csr[j + e]);
            uint2 v = __ldg(&hw[(size_t)idx * 8 + s]);
            acc0 = __hadd2(acc0, fp8x2_to_h2((unsigned short)(v.x & 0xffffu)));
            acc1 = __hadd2(acc1, fp8x2_to_h2((unsigned short)(v.x >> 16)));
            acc2 = __hadd2(acc2, fp8x2_to_h2((unsigned short)(v.y & 0xffffu)));
            acc3 = __hadd2(acc3, fp8x2_to_h2((unsigned short)(v.y >> 16)));
        }
        int rem = end - j;       // 0..3, warp-uniform
        if (e < rem) {
            int idx = __ldg(&g_csr[j + e]);
            uint2 v = __ldg(&hw[(size_t)idx * 8 + s]);
            acc0 = __hadd2(acc0, fp8x2_to_h2((unsigned short)(v.x & 0xffffu)));
            acc1 = __hadd2(acc1, fp8x2_to_h2((unsigned short)(v.x >> 16)));
            acc2 = __hadd2(acc2, fp8x2_to_h2((unsigned short)(v.y & 0xffffu)));
            acc3 = __hadd2(acc3, fp8x2_to_h2((unsigned short)(v.y >> 16)));
        }
    }

    // reduce across edge slots (xor 8, then 16); all lanes participate
    unsigned ua0 = *reinterpret_cast<unsigned*>(&acc0);
    unsigned ua1 = *reinterpret_cast<unsigned*>(&acc1);
    unsigned ua2 = *reinterpret_cast<unsigned*>(&acc2);
    unsigned ua3 = *reinterpret_cast<unsigned*>(&acc3);
    acc0 = __hadd2(u2h2(ua0), u2h2(__shfl_xor_sync(0xffffffffu, ua0, 8)));
    acc1 = __hadd2(u2h2(ua1), u2h2(__shfl_xor_sync(0xffffffffu, ua1, 8)));
    acc2 = __hadd2(u2h2(ua2), u2h2(__shfl_xor_sync(0xffffffffu, ua2, 8)));
    acc3 = __hadd2(u2h2(ua3), u2h2(__shfl_xor_sync(0xffffffffu, ua3, 8)));
    ua0 = *reinterpret_cast<unsigned*>(&acc0);
    ua1 = *reinterpret_cast<unsigned*>(&acc1);
    ua2 = *reinterpret_cast<unsigned*>(&acc2);
    ua3 = *reinterpret_cast<unsigned*>(&acc3);
    acc0 = __hadd2(u2h2(ua0), u2h2(__shfl_xor_sync(0xffffffffu, ua0, 16)));
    acc1 = __hadd2(u2h2(ua1), u2h2(__shfl_xor_sync(0xffffffffu, ua1, 16)));
    acc2 = __hadd2(u2h2(ua2), u2h2(__shfl_xor_sync(0xffffffffu, ua2, 16)));
    acc3 = __hadd2(u2h2(ua3), u2h2(__shfl_xor_sync(0xffffffffu, ua3, 16)));

    float o0 = 0.f, o1 = 0.f, o2 = 0.f, o3 = 0.f, o4 = 0.f, o5 = 0.f, o6 = 0.f, o7 = 0.f;
    if (valid && e == 0) {
        float di = g_dis[gw] * INV_MSG_SCALE;
        float4 bA = __ldg(reinterpret_cast<const float4*>(bias) + 2 * s);
        float4 bB = __ldg(reinterpret_cast<const float4*>(bias) + 2 * s + 1);
        float2 f0 = __half22float2(acc0), f1 = __half22float2(acc1);
        float2 f2 = __half22float2(acc2), f3 = __half22float2(acc3);
        o0 = fmaxf(fmaf(di, f0.x, bA.x), 0.f);
        o1 = fmaxf(fmaf(di, f0.y, bA.y), 0.f);
        o2 = fmaxf(fmaf(di, f1.x, bA.z), 0.f);
        o3 = fmaxf(fmaf(di, f1.y, bA.w), 0.f);
        o4 = fmaxf(fmaf(di, f2.x, bB.x), 0.f);
        o5 = fmaxf(fmaf(di, f2.y, bB.y), 0.f);
        o6 = fmaxf(fmaf(di, f3.x, bB.z), 0.f);
        o7 = fmaxf(fmaf(di, f3.y, bB.w), 0.f);
        if (!POOL) {
            __half2 h0 = __floats2half2_rn(o0, o1);
            __half2 h1 = __floats2half2_rn(o2, o3);
            __half2 h2 = __floats2half2_rn(o4, o5);
            __half2 h3 = __floats2half2_rn(o6, o7);
            uint4 st;
            st.x = *reinterpret_cast<unsigned*>(&h0);
            st.y = *reinterpret_cast<unsigned*>(&h1);
            st.z = *reinterpret_cast<unsigned*>(&h2);
            st.w = *reinterpret_cast<unsigned*>(&h3);
            *reinterpret_cast<uint4*>(outh + (size_t)gw * HDIM + s * 8) = st;
        }
    }

    if (POOL) {
        if (e == 0) {
            Psm[wid * HDIM + s * 8 + 0] = o0;
            Psm[wid * HDIM + s * 8 + 1] = o1;
            Psm[wid * HDIM + s * 8 + 2] = o2;
            Psm[wid * HDIM + s * 8 + 3] = o3;
            Psm[wid * HDIM + s * 8 + 4] = o4;
            Psm[wid * HDIM + s * 8 + 5] = o5;
            Psm[wid * HDIM + s * 8 + 6] = o6;
            Psm[wid * HDIM + s * 8 + 7] = o7;
        }
        __syncthreads();
        if (threadIdx.x < HDIM) {
            float sum = 0.f;
            #pragma unroll
            for (int wv = 0; wv < 8; wv++) sum += Psm[wv * HDIM + threadIdx.x];
            atomicAdd(&g_pool[threadIdx.x], sum);
        }
    }
}

// ---------------- head ------------------------------------------------------------
__global__ void k_head(const float* __restrict__ gf,
                       const float* __restrict__ w_glob, const float* __restrict__ b_glob,
                       const float* __restrict__ w_fc1, const float* __restrict__ b_fc1,
                       const float* __restrict__ w_fc2, const float* __restrict__ b_fc2,
                       float* __restrict__ out) {
    __shared__ float xc[2 * HDIM];
    __shared__ float t1[HDIM];
    int t = threadIdx.x;

    xc[t] = g_pool[t] * (1.0f / (float)N_NODES);

    float a = b_glob[t];
    #pragma unroll
    for (int k = 0; k < FGLOB; k++) a += gf[k] * w_glob[k * HDIM + t];
    xc[HDIM + t] = fmaxf(a, 0.f);
    __syncthreads();

    float u = b_fc1[t];
    #pragma unroll 8
    for (int k = 0; k < 2 * HDIM; k++) u += xc[k] * w_fc1[k * HDIM + t];
    t1[t] = fmaxf(u, 0.f);
    __syncthreads();

    float o = b_fc2[t];
    #pragma unroll 8
    for (int k = 0; k < HDIM; k++) o += t1[k] * w_fc2[k * OUTDIM + t];
    out[t] = o;
}

// ---------------- launch ------------------------------------------------------
extern "C" void kernel_launch(void* const* d_in, const int* in_sizes, int n_in,
                              void* d_out, int out_size) {
    const float* x      = (const float*)d_in[0];
    const int*   ei     = (const int*)  d_in[1];   // [2,E]: first E = src, next E = dst
    const float* gf     = (const float*)d_in[2];
    const float* w_node = (const float*)d_in[3];
    const float* b_node = (const float*)d_in[4];
    const float* w_glob = (const float*)d_in[5];
    const float* b_glob = (const float*)d_in[6];
    const float* w_c[3] = {(const float*)d_in[7], (const float*)d_in[9],  (const float*)d_in[11]};
    const float* b_c[3] = {(const float*)d_in[8], (const float*)d_in[10], (const float*)d_in[12]};
    const float* w_fc1  = (const float*)d_in[13];
    const float* b_fc1  = (const float*)d_in[14];
    const float* w_fc2  = (const float*)d_in[15];
    const float* b_fc2  = (const float*)d_in[16];
    float* out = (float*)d_out;

    __half *p_hf;
    unsigned int *p_hw8;
    int *p_cnt;
    cudaGetSymbolAddress((void**)&p_hf,  g_hf);
    cudaGetSymbolAddress((void**)&p_hw8, g_hw8);
    cudaGetSymbolAddress((void**)&p_cnt, g_cnt);

    static cudaStream_t s_side = nullptr;
    static cudaEvent_t  s_evFork = nullptr, s_evDis = nullptr, s_evFill = nullptr;
    if (!s_side) {
        cudaStreamCreateWithFlags(&s_side, cudaStreamNonBlocking);
        cudaEventCreateWithFlags(&s_evFork, cudaEventDisableTiming);
        cudaEventCreateWithFlags(&s_evDis,  cudaEventDisableTiming);
        cudaEventCreateWithFlags(&s_evFill, cudaEventDisableTiming);
    }

    const int TB = 256;
    const int HG = (N_NODES + 127) / 128;   // 782 blocks

    // fork: CSR build chain on side stream
    cudaEventRecord(s_evFork, 0);
    cudaStreamWaitEvent(s_side, s_evFork, 0);
    cudaMemsetAsync(p_cnt, 0, N_NODES * sizeof(int), s_side);
    k_count<<<(N_EDGES / 4 + TB - 1) / TB, TB, 0, s_side>>>(
        (const int4*)(ei + N_EDGES));
    k_scan1<<<N_SCAN_BLOCKS, SCAN_BS, 0, s_side>>>();           // writes dis
    cudaEventRecord(s_evDis, s_side);
    k_scan2<<<1, 128, 0, s_side>>>();                           // + pool zero
    k_fill <<<(N_EDGES / 4 + TB - 1) / TB, TB, 0, s_side>>>(
        (const int4*)ei, (const int4*)(ei + N_EDGES));
    cudaEventRecord(s_evFill, s_side);

    // layer 1: fused embed + transform (needs dis for the epilogue)
    cudaStreamWaitEvent(0, s_evDis, 0);
    k_hmma<true><<<HG, 256>>>(nullptr, w_c[0], x, w_node, b_node, p_hw8);

    // agg needs CSR
    cudaStreamWaitEvent(0, s_evFill, 0);
    k_agg<false><<<(N_NODES * 32 + TB - 1) / TB, TB>>>((const uint2*)p_hw8, b_c[0], p_hf);
    k_hmma<false><<<HG, 256>>>(p_hf, w_c[1], nullptr, nullptr, nullptr, p_hw8);
    k_agg<false><<<(N_NODES * 32 + TB - 1) / TB, TB>>>((const uint2*)p_hw8, b_c[1], p_hf);
    k_hmma<false><<<HG, 256>>>(p_hf, w_c[2], nullptr, nullptr, nullptr, p_hw8);
    // layer-3 aggregation fused with mean pool
    k_agg<true ><<<(N_NODES * 32 + TB - 1) / TB, TB>>>((const uint2*)p_hw8, b_c[2], nullptr);

    k_head<<<1, 64>>>(gf, w_glob, b_glob, w_fc1, b_fc1, w_fc2, b_fc2, out);
}

// round 12
// speedup vs baseline: 1.1012x; 1.0759x over previous
#include <cuda_runtime.h>
#include <cuda_fp16.h>
#include <cuda_fp8.h>
#include <cstdint>

#define N_NODES 100000
#define N_EDGES 1600000
#define FNODE   32
#define FGLOB   16
#define HDIM    64
#define OUTDIM  64
#define MAXDEG  128    // Poisson(16) max over 100k nodes ~50; 128 is a >=8-sigma bound

#define MSG_SCALE     64.0f
#define INV_MSG_SCALE (1.0f / 64.0f)

// ---------------- scratch (device globals: no allocations allowed) ----------
__device__ int g_cnt[N_NODES];                                   // degree; fill cursor
__device__ __align__(16) int g_csr[(size_t)N_NODES * MAXDEG];    // slot-based CSR
__device__ __align__(16) __half g_hf[(size_t)N_NODES * HDIM];    // node features fp16
__device__ __align__(16) unsigned int g_hw8[(size_t)N_NODES * 16]; // fp8x4 msgs, 64B/row
__device__ float g_pool[HDIM];

// ---------------- fused count+fill: slot-based CSR (one atomic per edge) ---------
__global__ void k_fill(const int* __restrict__ src, const int* __restrict__ dst) {
    int e = blockIdx.x * blockDim.x + threadIdx.x;
    if (e < N_EDGES) {
        int d = dst[e];
        int slot = atomicAdd(&g_cnt[d], 1);
        g_csr[(size_t)d * MAXDEG + slot] = src[e];
    }
    if (e < HDIM) g_pool[e] = 0.f;    // piggyback pool zeroing (block 0)
}

// ---------------- fp8x2 -> half2 helpers -----------------------------------------
__device__ __forceinline__ __half2 fp8x2_to_h2(unsigned short u) {
    __half2_raw hr = __nv_cvt_fp8x2_to_halfraw2(u, __NV_E4M3);
    return *reinterpret_cast<__half2*>(&hr);
}
__device__ __forceinline__ __half2 u2h2(unsigned int u) {
    return *reinterpret_cast<__half2*>(&u);
}

#define APITCH 72      // halves; conflict-free ldmatrix
#define S8P    36      // ushorts per padded fp8 row (32 data + 4 pad)

// ---------------- HMMA conv transform: hw8 = fp8(64 * dis .* (A @ W)) ------------
// Block: 256 threads = 8 warps, 128 rows. EMBED: A = fp16(x @ Wn + bn) in-block.
// dis computed inline from g_cnt (final after k_fill).
template<bool EMBED>
__global__ void k_hmma(const __half* __restrict__ hin, const float* __restrict__ w,
                       const float* __restrict__ xin, const float* __restrict__ wn,
                       const float* __restrict__ bn,
                       unsigned int* __restrict__ out8) {
    __shared__ __half Wsm[HDIM * APITCH];
    __shared__ __half Asm[128 * APITCH];
    __shared__ float WnS[EMBED ? FNODE * HDIM : 1];
    __shared__ float BnS[EMBED ? HDIM : 1];
    int tid = threadIdx.x;
    int lane = tid & 31, wid = tid >> 5;
    int rowBase = blockIdx.x * 128;

    for (int i = tid; i < HDIM * HDIM; i += 256) {
        int r = i >> 6, c = i & 63;
        Wsm[r * APITCH + c] = __float2half(w[i]);
    }

    if (EMBED) {
        for (int i = tid; i < FNODE * HDIM / 4; i += 256)
            reinterpret_cast<float4*>(WnS)[i] = reinterpret_cast<const float4*>(wn)[i];
        if (tid < HDIM) BnS[tid] = bn[tid];
        __syncthreads();

        int row = tid >> 1;
        int colBase = (tid & 1) * 32;
        int gr = rowBase + row;
        float acc[32];
        #pragma unroll
        for (int c = 0; c < 32; c++) acc[c] = 0.f;
        if (gr < N_NODES) {
            const float4* xr = reinterpret_cast<const float4*>(xin + (size_t)gr * FNODE);
            #pragma unroll
            for (int k4 = 0; k4 < FNODE / 4; ++k4) {
                float4 a = __ldg(&xr[k4]);
                const float av[4] = {a.x, a.y, a.z, a.w};
                #pragma unroll
                for (int kk = 0; kk < 4; ++kk) {
                    const float4* wrow = reinterpret_cast<const float4*>(
                        &WnS[(k4 * 4 + kk) * HDIM + colBase]);
                    float xa = av[kk];
                    #pragma unroll
                    for (int c4 = 0; c4 < 8; c4++) {
                        float4 wv = wrow[c4];
                        acc[c4*4+0] += xa * wv.x;
                        acc[c4*4+1] += xa * wv.y;
                        acc[c4*4+2] += xa * wv.z;
                        acc[c4*4+3] += xa * wv.w;
                    }
                }
            }
        }
        #pragma unroll
        for (int c2 = 0; c2 < 16; c2++) {
            __half2 hv = __floats2half2_rn(acc[2*c2]   + BnS[colBase + 2*c2],
                                           acc[2*c2+1] + BnS[colBase + 2*c2 + 1]);
            *reinterpret_cast<__half2*>(&Asm[row * APITCH + colBase + 2*c2]) = hv;
        }
    } else {
        for (int i = tid; i < 128 * 16; i += 256) {
            int r = i >> 4, c4 = i & 15;
            int gr = rowBase + r;
            uint2 v = make_uint2(0u, 0u);
            if (gr < N_NODES)
                v = *reinterpret_cast<const uint2*>(hin + (size_t)gr * HDIM + c4 * 4);
            *reinterpret_cast<uint2*>(&Asm[r * APITCH + c4 * 4]) = v;
        }
    }
    __syncthreads();

    float acc[8][4];
    #pragma unroll
    for (int j = 0; j < 8; j++)
        #pragma unroll
        for (int q = 0; q < 4; q++) acc[j][q] = 0.f;

    uint32_t aAddr = (uint32_t)__cvta_generic_to_shared(
        &Asm[(wid * 16 + (lane & 15)) * APITCH + (lane >> 4) * 8]);
    uint32_t bAddr = (uint32_t)__cvta_generic_to_shared(
        &Wsm[(lane & 15) * APITCH]);

    #pragma unroll
    for (int k = 0; k < 4; k++) {
        uint32_t a0, a1, a2, a3;
        asm volatile("ldmatrix.sync.aligned.m8n8.x4.shared.b16 {%0,%1,%2,%3}, [%4];\n"
                     : "=r"(a0), "=r"(a1), "=r"(a2), "=r"(a3)
                     : "r"(aAddr + k * 16 * 2));
        #pragma unroll
        for (int j = 0; j < 8; j++) {
            uint32_t b0, b1;
            asm volatile("ldmatrix.sync.aligned.m8n8.x2.trans.shared.b16 {%0,%1}, [%2];\n"
                         : "=r"(b0), "=r"(b1)
                         : "r"(bAddr + (k * 16 * APITCH + j * 8) * 2));
            asm volatile("mma.sync.aligned.m16n8k16.row.col.f32.f16.f16.f32 "
                         "{%0,%1,%2,%3}, {%4,%5,%6,%7}, {%8,%9}, {%0,%1,%2,%3};\n"
                         : "+f"(acc[j][0]), "+f"(acc[j][1]), "+f"(acc[j][2]), "+f"(acc[j][3])
                         : "r"(a0), "r"(a1), "r"(a2), "r"(a3), "r"(b0), "r"(b1));
        }
    }

    __syncthreads();
    unsigned short* S8 = reinterpret_cast<unsigned short*>(Asm);   // [128][S8P]

    int g = lane >> 2, q = lane & 3;
    int r0l = wid * 16 + g;
    int r1l = r0l + 8;
    int gr0 = rowBase + r0l, gr1 = rowBase + r1l;
    float d0 = (gr0 < N_NODES) ? rsqrtf((float)(g_cnt[gr0] + 1)) * MSG_SCALE : 0.f;
    float d1 = (gr1 < N_NODES) ? rsqrtf((float)(g_cnt[gr1] + 1)) * MSG_SCALE : 0.f;
    #pragma unroll
    for (int j = 0; j < 8; j++) {
        S8[r0l * S8P + j * 4 + q] = __nv_cvt_float2_to_fp8x2(
            make_float2(acc[j][0] * d0, acc[j][1] * d0), __NV_SATFINITE, __NV_E4M3);
        S8[r1l * S8P + j * 4 + q] = __nv_cvt_float2_to_fp8x2(
            make_float2(acc[j][2] * d1, acc[j][3] * d1), __NV_SATFINITE, __NV_E4M3);
    }
    __syncthreads();

    for (int i = tid; i < 128 * 8; i += 256) {
        int r = i >> 3, c = i & 7;
        int grow = rowBase + r;
        if (grow < N_NODES) {
            uint2 v = *reinterpret_cast<const uint2*>(&S8[r * S8P + c * 4]);
            *reinterpret_cast<uint2*>(&out8[(size_t)grow * 16 + c * 2]) = v;
        }
    }
}

// ---------------- aggregation: warp/node, 8 lanes/row, 4 edges per LDG ----------
// hw8 rows (64B) pre-scaled by 64*dis[src]. hf[i] = fp16(relu(dis[i]/64*sum + b))
__global__ void k_agg(const uint2* __restrict__ hw,
                      const float* __restrict__ bias, __half* __restrict__ outh) {
    int gw = (blockIdx.x * blockDim.x + threadIdx.x) >> 5;
    int lane = threadIdx.x & 31;
    if (gw >= N_NODES) return;
    int e = lane >> 3;           // edge slot 0..3
    int s = lane & 7;            // uint2 column (8 fp8 cols)

    __half2 acc0 = __float2half2_rn(0.f), acc1 = acc0, acc2 = acc0, acc3 = acc0;

    if (e == 0) {                // self loop
        uint2 v = __ldg(&hw[(size_t)gw * 8 + s]);
        acc0 = fp8x2_to_h2((unsigned short)(v.x & 0xffffu));
        acc1 = fp8x2_to_h2((unsigned short)(v.x >> 16));
        acc2 = fp8x2_to_h2((unsigned short)(v.y & 0xffffu));
        acc3 = fp8x2_to_h2((unsigned short)(v.y >> 16));
    }

    int cnt = g_cnt[gw];
    const int* row = g_csr + (size_t)gw * MAXDEG;
    int j = 0;
    for (; j + 4 <= cnt; j += 4) {
        int idx = __ldg(&row[j + e]);
        uint2 v = __ldg(&hw[(size_t)idx * 8 + s]);
        acc0 = __hadd2(acc0, fp8x2_to_h2((unsigned short)(v.x & 0xffffu)));
        acc1 = __hadd2(acc1, fp8x2_to_h2((unsigned short)(v.x >> 16)));
        acc2 = __hadd2(acc2, fp8x2_to_h2((unsigned short)(v.y & 0xffffu)));
        acc3 = __hadd2(acc3, fp8x2_to_h2((unsigned short)(v.y >> 16)));
    }
    int rem = cnt - j;           // 0..3, warp-uniform
    if (e < rem) {
        int idx = __ldg(&row[j + e]);
        uint2 v = __ldg(&hw[(size_t)idx * 8 + s]);
        acc0 = __hadd2(acc0, fp8x2_to_h2((unsigned short)(v.x & 0xffffu)));
        acc1 = __hadd2(acc1, fp8x2_to_h2((unsigned short)(v.x >> 16)));
        acc2 = __hadd2(acc2, fp8x2_to_h2((unsigned short)(v.y & 0xffffu)));
        acc3 = __hadd2(acc3, fp8x2_to_h2((unsigned short)(v.y >> 16)));
    }

    // reduce across edge slots (xor 8, then 16)
    unsigned ua0 = *reinterpret_cast<unsigned*>(&acc0);
    unsigned ua1 = *reinterpret_cast<unsigned*>(&acc1);
    unsigned ua2 = *reinterpret_cast<unsigned*>(&acc2);
    unsigned ua3 = *reinterpret_cast<unsigned*>(&acc3);
    acc0 = __hadd2(u2h2(ua0), u2h2(__shfl_xor_sync(0xffffffffu, ua0, 8)));
    acc1 = __hadd2(u2h2(ua1), u2h2(__shfl_xor_sync(0xffffffffu, ua1, 8)));
    acc2 = __hadd2(u2h2(ua2), u2h2(__shfl_xor_sync(0xffffffffu, ua2, 8)));
    acc3 = __hadd2(u2h2(ua3), u2h2(__shfl_xor_sync(0xffffffffu, ua3, 8)));
    ua0 = *reinterpret_cast<unsigned*>(&acc0);
    ua1 = *reinterpret_cast<unsigned*>(&acc1);
    ua2 = *reinterpret_cast<unsigned*>(&acc2);
    ua3 = *reinterpret_cast<unsigned*>(&acc3);
    acc0 = __hadd2(u2h2(ua0), u2h2(__shfl_xor_sync(0xffffffffu, ua0, 16)));
    acc1 = __hadd2(u2h2(ua1), u2h2(__shfl_xor_sync(0xffffffffu, ua1, 16)));
    acc2 = __hadd2(u2h2(ua2), u2h2(__shfl_xor_sync(0xffffffffu, ua2, 16)));
    acc3 = __hadd2(u2h2(ua3), u2h2(__shfl_xor_sync(0xffffffffu, ua3, 16)));

    if (e == 0) {
        float di = rsqrtf((float)(cnt + 1)) * INV_MSG_SCALE;
        float4 bA = __ldg(reinterpret_cast<const float4*>(bias) + 2 * s);
        float4 bB = __ldg(reinterpret_cast<const float4*>(bias) + 2 * s + 1);
        float2 f0 = __half22float2(acc0), f1 = __half22float2(acc1);
        float2 f2 = __half22float2(acc2), f3 = __half22float2(acc3);
        __half2 h0 = __floats2half2_rn(fmaxf(fmaf(di, f0.x, bA.x), 0.f),
                                       fmaxf(fmaf(di, f0.y, bA.y), 0.f));
        __half2 h1 = __floats2half2_rn(fmaxf(fmaf(di, f1.x, bA.z), 0.f),
                                       fmaxf(fmaf(di, f1.y, bA.w), 0.f));
        __half2 h2 = __floats2half2_rn(fmaxf(fmaf(di, f2.x, bB.x), 0.f),
                                       fmaxf(fmaf(di, f2.y, bB.y), 0.f));
        __half2 h3 = __floats2half2_rn(fmaxf(fmaf(di, f3.x, bB.z), 0.f),
                                       fmaxf(fmaf(di, f3.y, bB.w), 0.f));
        uint4 st;
        st.x = *reinterpret_cast<unsigned*>(&h0);
        st.y = *reinterpret_cast<unsigned*>(&h1);
        st.z = *reinterpret_cast<unsigned*>(&h2);
        st.w = *reinterpret_cast<unsigned*>(&h3);
        *reinterpret_cast<uint4*>(outh + (size_t)gw * HDIM + s * 8) = st;
    }
}

// ---------------- mean pool over nodes (fp16 input) ------------------------------
__global__ void k_pool(const __half2* __restrict__ h2) {
    __shared__ float2 sh[256];
    int c = threadIdx.x & 31;       // half2 column
    int seg = threadIdx.x >> 5;     // 0..7
    float2 acc = make_float2(0.f, 0.f);
    for (int r = blockIdx.x * 8 + seg; r < N_NODES; r += gridDim.x * 8) {
        float2 v = __half22float2(h2[(size_t)r * 32 + c]);
        acc.x += v.x; acc.y += v.y;
    }
    sh[threadIdx.x] = acc;
    __syncthreads();
    if (threadIdx.x < 32) {
        float2 s = sh[c];
        #pragma unroll
        for (int k = 1; k < 8; k++) {
            s.x += sh[k * 32 + c].x;
            s.y += sh[k * 32 + c].y;
        }
        atomicAdd(&g_pool[2 * c],     s.x);
        atomicAdd(&g_pool[2 * c + 1], s.y);
    }
}

// ---------------- head ------------------------------------------------------------
__global__ void k_head(const float* __restrict__ gf,
                       const float* __restrict__ w_glob, const float* __restrict__ b_glob,
                       const float* __restrict__ w_fc1, const float* __restrict__ b_fc1,
                       const float* __restrict__ w_fc2, const float* __restrict__ b_fc2,
                       float* __restrict__ out) {
    __shared__ float xc[2 * HDIM];
    __shared__ float t1[HDIM];
    int t = threadIdx.x;

    xc[t] = g_pool[t] * (1.0f / (float)N_NODES);

    float a = b_glob[t];
    #pragma unroll
    for (int k = 0; k < FGLOB; k++) a += gf[k] * w_glob[k * HDIM + t];
    xc[HDIM + t] = fmaxf(a, 0.f);
    __syncthreads();

    float u = b_fc1[t];
    #pragma unroll 8
    for (int k = 0; k < 2 * HDIM; k++) u += xc[k] * w_fc1[k * HDIM + t];
    t1[t] = fmaxf(u, 0.f);
    __syncthreads();

    float o = b_fc2[t];
    #pragma unroll 8
    for (int k = 0; k < HDIM; k++) o += t1[k] * w_fc2[k * OUTDIM + t];
    out[t] = o;
}

// ---------------- launch ------------------------------------------------------
extern "C" void kernel_launch(void* const* d_in, const int* in_sizes, int n_in,
                              void* d_out, int out_size) {
    const float* x      = (const float*)d_in[0];
    const int*   ei     = (const int*)  d_in[1];   // [2,E]: first E = src, next E = dst
    const float* gf     = (const float*)d_in[2];
    const float* w_node = (const float*)d_in[3];
    const float* b_node = (const float*)d_in[4];
    const float* w_glob = (const float*)d_in[5];
    const float* b_glob = (const float*)d_in[6];
    const float* w_c[3] = {(const float*)d_in[7], (const float*)d_in[9],  (const float*)d_in[11]};
    const float* b_c[3] = {(const float*)d_in[8], (const float*)d_in[10], (const float*)d_in[12]};
    const float* w_fc1  = (const float*)d_in[13];
    const float* b_fc1  = (const float*)d_in[14];
    const float* w_fc2  = (const float*)d_in[15];
    const float* b_fc2  = (const float*)d_in[16];
    float* out = (float*)d_out;

    __half *p_hf;
    unsigned int *p_hw8;
    int *p_cnt;
    cudaGetSymbolAddress((void**)&p_hf,  g_hf);
    cudaGetSymbolAddress((void**)&p_hw8, g_hw8);
    cudaGetSymbolAddress((void**)&p_cnt, g_cnt);

    const int TB = 256;
    const int HG = (N_NODES + 127) / 128;   // 782 blocks

    // CSR build: zero degrees, then one-pass slot fill (count implicit)
    cudaMemsetAsync(p_cnt, 0, N_NODES * sizeof(int));
    k_fill<<<(N_EDGES + TB - 1) / TB, TB>>>(ei, ei + N_EDGES);

    // layer 1: fused embed + transform (dis inline from cnt)
    k_hmma<true><<<HG, 256>>>(nullptr, w_c[0], x, w_node, b_node, p_hw8);
    k_agg<<<(N_NODES * 32 + TB - 1) / TB, TB>>>((const uint2*)p_hw8, b_c[0], p_hf);

    for (int l = 1; l < 3; l++) {
        k_hmma<false><<<HG, 256>>>(p_hf, w_c[l], nullptr, nullptr, nullptr, p_hw8);
        k_agg<<<(N_NODES * 32 + TB - 1) / TB, TB>>>((const uint2*)p_hw8, b_c[l], p_hf);
    }

    // pool + head
    k_pool<<<256, 256>>>((const __half2*)p_hf);
    k_head<<<1, 64>>>(gf, w_glob, b_glob, w_fc1, b_fc1, w_fc2, b_fc2, out);
}

// round 13
// speedup vs baseline: 1.1797x; 1.0713x over previous
#include <cuda_runtime.h>
#include <cuda_fp16.h>
#include <cuda_fp8.h>
#include <cstdint>

#define N_NODES 100000
#define N_EDGES 1600000
#define FNODE   32
#define FGLOB   16
#define HDIM    64
#define OUTDIM  64
#define MAXDEG  128    // Poisson(16) max over 100k nodes ~50; 128 is a >=8-sigma bound

#define MSG_SCALE     64.0f
#define INV_MSG_SCALE (1.0f / 64.0f)

// ---------------- scratch (device globals: no allocations allowed) ----------
__device__ int   g_cnt[N_NODES];                                 // degree; fill cursor
__device__ __align__(16) int g_csr[(size_t)N_NODES * MAXDEG];    // slot-based CSR
__device__ float g_dis[N_NODES];
__device__ __align__(16) __half g_wh[3][HDIM * HDIM];            // fp16 conv weights
__device__ __align__(16) __half g_hf[(size_t)N_NODES * HDIM];    // node features fp16
__device__ __align__(16) unsigned int g_hw8[(size_t)N_NODES * 16]; // fp8x4 msgs, 64B/row
__device__ float g_pool[HDIM];

// ---------------- W pre-convert: fp32 -> fp16 for 3 conv layers ------------------
__global__ void k_prep(const float* __restrict__ w0, const float* __restrict__ w1,
                       const float* __restrict__ w2) {
    int i = blockIdx.x * blockDim.x + threadIdx.x;   // 0 .. 3*4096-1
    if (i < HDIM * HDIM)          g_wh[0][i] = __float2half(w0[i]);
    else if (i < 2 * HDIM * HDIM) g_wh[1][i - HDIM * HDIM] = __float2half(w1[i - HDIM * HDIM]);
    else if (i < 3 * HDIM * HDIM) g_wh[2][i - 2 * HDIM * HDIM] = __float2half(w2[i - 2 * HDIM * HDIM]);
}

// ---------------- fused count+fill: slot-based CSR (one atomic per edge) ---------
__global__ void k_fill(const int* __restrict__ src, const int* __restrict__ dst) {
    int e = blockIdx.x * blockDim.x + threadIdx.x;
    if (e < N_EDGES) {
        int d = dst[e];
        int slot = atomicAdd(&g_cnt[d], 1);
        g_csr[(size_t)d * MAXDEG + slot] = src[e];
    }
}

// ---------------- dis = rsqrt(cnt+1) + pool zero ----------------------------------
__global__ void k_dis() {
    int i = blockIdx.x * blockDim.x + threadIdx.x;
    if (i < N_NODES) g_dis[i] = rsqrtf((float)(g_cnt[i] + 1));
    if (i < HDIM) g_pool[i] = 0.f;
}

// ---------------- fp8x2 -> half2 helpers -----------------------------------------
__device__ __forceinline__ __half2 fp8x2_to_h2(unsigned short u) {
    __half2_raw hr = __nv_cvt_fp8x2_to_halfraw2(u, __NV_E4M3);
    return *reinterpret_cast<__half2*>(&hr);
}
__device__ __forceinline__ __half2 u2h2(unsigned int u) {
    return *reinterpret_cast<__half2*>(&u);
}

#define APITCH 72      // halves; conflict-free ldmatrix (144B rows)
#define S8P    36      // ushorts per padded fp8 row (32 data + 4 pad)

// ---------------- HMMA conv transform ---------------------------------------------
// EMBED=true : A = fp16(x @ Wn + bn) in-block; msgs UNSCALED: fp8(64 * (A @ W))
// EMBED=false: A = hf rows;            msgs pre-scaled:  fp8(64 * dis * (A @ W))
template<bool EMBED>
__global__ void k_hmma(const __half* __restrict__ hin, const __half* __restrict__ wh,
                       const float* __restrict__ xin, const float* __restrict__ wn,
                       const float* __restrict__ bn,
                       unsigned int* __restrict__ out8) {
    __shared__ __half Wsm[HDIM * APITCH];
    __shared__ __half Asm[128 * APITCH];
    __shared__ float WnS[EMBED ? FNODE * HDIM : 1];
    __shared__ float BnS[EMBED ? HDIM : 1];
    int tid = threadIdx.x;
    int lane = tid & 31, wid = tid >> 5;
    int rowBase = blockIdx.x * 128;

    // stage W (fp16, uint4 = 8 halves; 512 uint4 total)
    for (int i = tid; i < HDIM * 8; i += 256) {
        int r = i >> 3, c8 = i & 7;
        *reinterpret_cast<uint4*>(&Wsm[r * APITCH + c8 * 8]) =
            *reinterpret_cast<const uint4*>(wh + r * HDIM + c8 * 8);
    }

    if (EMBED) {
        for (int i = tid; i < FNODE * HDIM / 4; i += 256)
            reinterpret_cast<float4*>(WnS)[i] = reinterpret_cast<const float4*>(wn)[i];
        if (tid < HDIM) BnS[tid] = bn[tid];
        __syncthreads();

        int row = tid >> 1;
        int colBase = (tid & 1) * 32;
        int gr = rowBase + row;
        float acc[32];
        #pragma unroll
        for (int c = 0; c < 32; c++) acc[c] = 0.f;
        if (gr < N_NODES) {
            const float4* xr = reinterpret_cast<const float4*>(xin + (size_t)gr * FNODE);
            #pragma unroll
            for (int k4 = 0; k4 < FNODE / 4; ++k4) {
                float4 a = __ldg(&xr[k4]);
                const float av[4] = {a.x, a.y, a.z, a.w};
                #pragma unroll
                for (int kk = 0; kk < 4; ++kk) {
                    const float4* wrow = reinterpret_cast<const float4*>(
                        &WnS[(k4 * 4 + kk) * HDIM + colBase]);
                    float xa = av[kk];
                    #pragma unroll
                    for (int c4 = 0; c4 < 8; c4++) {
                        float4 wv = wrow[c4];
                        acc[c4*4+0] += xa * wv.x;
                        acc[c4*4+1] += xa * wv.y;
                        acc[c4*4+2] += xa * wv.z;
                        acc[c4*4+3] += xa * wv.w;
                    }
                }
            }
        }
        #pragma unroll
        for (int c2 = 0; c2 < 16; c2++) {
            __half2 hv = __floats2half2_rn(acc[2*c2]   + BnS[colBase + 2*c2],
                                           acc[2*c2+1] + BnS[colBase + 2*c2 + 1]);
            *reinterpret_cast<__half2*>(&Asm[row * APITCH + colBase + 2*c2]) = hv;
        }
    } else {
        // stage A rows (uint4 = 8 halves; 1024 uint4 total)
        for (int i = tid; i < 128 * 8; i += 256) {
            int r = i >> 3, c8 = i & 7;
            int gr = rowBase + r;
            uint4 v = make_uint4(0u, 0u, 0u, 0u);
            if (gr < N_NODES)
                v = *reinterpret_cast<const uint4*>(hin + (size_t)gr * HDIM + c8 * 8);
            *reinterpret_cast<uint4*>(&Asm[r * APITCH + c8 * 8]) = v;
        }
    }
    __syncthreads();

    float acc[8][4];
    #pragma unroll
    for (int j = 0; j < 8; j++)
        #pragma unroll
        for (int q = 0; q < 4; q++) acc[j][q] = 0.f;

    uint32_t aAddr = (uint32_t)__cvta_generic_to_shared(
        &Asm[(wid * 16 + (lane & 15)) * APITCH + (lane >> 4) * 8]);
    uint32_t bAddr = (uint32_t)__cvta_generic_to_shared(
        &Wsm[(lane & 15) * APITCH]);

    #pragma unroll
    for (int k = 0; k < 4; k++) {
        uint32_t a0, a1, a2, a3;
        asm volatile("ldmatrix.sync.aligned.m8n8.x4.shared.b16 {%0,%1,%2,%3}, [%4];\n"
                     : "=r"(a0), "=r"(a1), "=r"(a2), "=r"(a3)
                     : "r"(aAddr + k * 16 * 2));
        #pragma unroll
        for (int j = 0; j < 8; j++) {
            uint32_t b0, b1;
            asm volatile("ldmatrix.sync.aligned.m8n8.x2.trans.shared.b16 {%0,%1}, [%2];\n"
                         : "=r"(b0), "=r"(b1)
                         : "r"(bAddr + (k * 16 * APITCH + j * 8) * 2));
            asm volatile("mma.sync.aligned.m16n8k16.row.col.f32.f16.f16.f32 "
                         "{%0,%1,%2,%3}, {%4,%5,%6,%7}, {%8,%9}, {%0,%1,%2,%3};\n"
                         : "+f"(acc[j][0]), "+f"(acc[j][1]), "+f"(acc[j][2]), "+f"(acc[j][3])
                         : "r"(a0), "r"(a1), "r"(a2), "r"(a3), "r"(b0), "r"(b1));
        }
    }

    __syncthreads();
    unsigned short* S8 = reinterpret_cast<unsigned short*>(Asm);   // [128][S8P]

    int g = lane >> 2, q = lane & 3;
    int r0l = wid * 16 + g;
    int r1l = r0l + 8;
    int gr0 = rowBase + r0l, gr1 = rowBase + r1l;
    float d0, d1;
    if (EMBED) {                       // unscaled messages (dis applied in agg)
        d0 = MSG_SCALE; d1 = MSG_SCALE;
    } else {
        d0 = (gr0 < N_NODES) ? g_dis[gr0] * MSG_SCALE : 0.f;
        d1 = (gr1 < N_NODES) ? g_dis[gr1] * MSG_SCALE : 0.f;
    }
    #pragma unroll
    for (int j = 0; j < 8; j++) {
        S8[r0l * S8P + j * 4 + q] = __nv_cvt_float2_to_fp8x2(
            make_float2(acc[j][0] * d0, acc[j][1] * d0), __NV_SATFINITE, __NV_E4M3);
        S8[r1l * S8P + j * 4 + q] = __nv_cvt_float2_to_fp8x2(
            make_float2(acc[j][2] * d1, acc[j][3] * d1), __NV_SATFINITE, __NV_E4M3);
    }
    __syncthreads();

    for (int i = tid; i < 128 * 8; i += 256) {
        int r = i >> 3, c = i & 7;
        int grow = rowBase + r;
        if (grow < N_NODES) {
            uint2 v = *reinterpret_cast<const uint2*>(&S8[r * S8P + c * 4]);
            *reinterpret_cast<uint2*>(&out8[(size_t)grow * 16 + c * 2]) = v;
        }
    }
}

// ---------------- aggregation: warp/node, 8 lanes/row, 4 edges per LDG -----------
// EDIS=true : msgs unscaled -> per-edge dis[src] applied via hfma2 (layer 1)
// EDIS=false: msgs pre-scaled by dis[src] (layers 2,3)
// hf[i] = fp16(relu(dis[i]/64 * sum + b))
template<bool EDIS>
__global__ void k_agg(const uint2* __restrict__ hw,
                      const float* __restrict__ bias, __half* __restrict__ outh) {
    int gw = (blockIdx.x * blockDim.x + threadIdx.x) >> 5;
    int lane = threadIdx.x & 31;
    if (gw >= N_NODES) return;
    int e = lane >> 3;           // edge slot 0..3
    int s = lane & 7;            // uint2 column (8 fp8 cols)

    float disg = __ldg(&g_dis[gw]);

    __half2 acc0 = __float2half2_rn(0.f), acc1 = acc0, acc2 = acc0, acc3 = acc0;

    if (e == 0) {                // self loop
        uint2 v = __ldg(&hw[(size_t)gw * 8 + s]);
        __half2 v0 = fp8x2_to_h2((unsigned short)(v.x & 0xffffu));
        __half2 v1 = fp8x2_to_h2((unsigned short)(v.x >> 16));
        __half2 v2 = fp8x2_to_h2((unsigned short)(v.y & 0xffffu));
        __half2 v3 = fp8x2_to_h2((unsigned short)(v.y >> 16));
        if (EDIS) {
            __half2 dh = __float2half2_rn(disg);
            acc0 = __hmul2(v0, dh); acc1 = __hmul2(v1, dh);
            acc2 = __hmul2(v2, dh); acc3 = __hmul2(v3, dh);
        } else {
            acc0 = v0; acc1 = v1; acc2 = v2; acc3 = v3;
        }
    }

    int cnt = g_cnt[gw];
    const int* row = g_csr + (size_t)gw * MAXDEG;
    int j = 0;
    for (; j + 4 <= cnt; j += 4) {
        int idx = __ldg(&row[j + e]);
        uint2 v = __ldg(&hw[(size_t)idx * 8 + s]);
        __half2 v0 = fp8x2_to_h2((unsigned short)(v.x & 0xffffu));
        __half2 v1 = fp8x2_to_h2((unsigned short)(v.x >> 16));
        __half2 v2 = fp8x2_to_h2((unsigned short)(v.y & 0xffffu));
        __half2 v3 = fp8x2_to_h2((unsigned short)(v.y >> 16));
        if (EDIS) {
            __half2 dh = __float2half2_rn(__ldg(&g_dis[idx]));
            acc0 = __hfma2(v0, dh, acc0); acc1 = __hfma2(v1, dh, acc1);
            acc2 = __hfma2(v2, dh, acc2); acc3 = __hfma2(v3, dh, acc3);
        } else {
            acc0 = __hadd2(acc0, v0); acc1 = __hadd2(acc1, v1);
            acc2 = __hadd2(acc2, v2); acc3 = __hadd2(acc3, v3);
        }
    }
    int rem = cnt - j;           // 0..3, warp-uniform
    if (e < rem) {
        int idx = __ldg(&row[j + e]);
        uint2 v = __ldg(&hw[(size_t)idx * 8 + s]);
        __half2 v0 = fp8x2_to_h2((unsigned short)(v.x & 0xffffu));
        __half2 v1 = fp8x2_to_h2((unsigned short)(v.x >> 16));
        __half2 v2 = fp8x2_to_h2((unsigned short)(v.y & 0xffffu));
        __half2 v3 = fp8x2_to_h2((unsigned short)(v.y >> 16));
        if (EDIS) {
            __half2 dh = __float2half2_rn(__ldg(&g_dis[idx]));
            acc0 = __hfma2(v0, dh, acc0); acc1 = __hfma2(v1, dh, acc1);
            acc2 = __hfma2(v2, dh, acc2); acc3 = __hfma2(v3, dh, acc3);
        } else {
            acc0 = __hadd2(acc0, v0); acc1 = __hadd2(acc1, v1);
            acc2 = __hadd2(acc2, v2); acc3 = __hadd2(acc3, v3);
        }
    }

    // reduce across edge slots (xor 8, then 16)
    unsigned ua0 = *reinterpret_cast<unsigned*>(&acc0);
    unsigned ua1 = *reinterpret_cast<unsigned*>(&acc1);
    unsigned ua2 = *reinterpret_cast<unsigned*>(&acc2);
    unsigned ua3 = *reinterpret_cast<unsigned*>(&acc3);
    acc0 = __hadd2(u2h2(ua0), u2h2(__shfl_xor_sync(0xffffffffu, ua0, 8)));
    acc1 = __hadd2(u2h2(ua1), u2h2(__shfl_xor_sync(0xffffffffu, ua1, 8)));
    acc2 = __hadd2(u2h2(ua2), u2h2(__shfl_xor_sync(0xffffffffu, ua2, 8)));
    acc3 = __hadd2(u2h2(ua3), u2h2(__shfl_xor_sync(0xffffffffu, ua3, 8)));
    ua0 = *reinterpret_cast<unsigned*>(&acc0);
    ua1 = *reinterpret_cast<unsigned*>(&acc1);
    ua2 = *reinterpret_cast<unsigned*>(&acc2);
    ua3 = *reinterpret_cast<unsigned*>(&acc3);
    acc0 = __hadd2(u2h2(ua0), u2h2(__shfl_xor_sync(0xffffffffu, ua0, 16)));
    acc1 = __hadd2(u2h2(ua1), u2h2(__shfl_xor_sync(0xffffffffu, ua1, 16)));
    acc2 = __hadd2(u2h2(ua2), u2h2(__shfl_xor_sync(0xffffffffu, ua2, 16)));
    acc3 = __hadd2(u2h2(ua3), u2h2(__shfl_xor_sync(0xffffffffu, ua3, 16)));

    if (e == 0) {
        float di = disg * INV_MSG_SCALE;
        float4 bA = __ldg(reinterpret_cast<const float4*>(bias) + 2 * s);
        float4 bB = __ldg(reinterpret_cast<const float4*>(bias) + 2 * s + 1);
        float2 f0 = __half22float2(acc0), f1 = __half22float2(acc1);
        float2 f2 = __half22float2(acc2), f3 = __half22float2(acc3);
        __half2 h0 = __floats2half2_rn(fmaxf(fmaf(di, f0.x, bA.x), 0.f),
                                       fmaxf(fmaf(di, f0.y, bA.y), 0.f));
        __half2 h1 = __floats2half2_rn(fmaxf(fmaf(di, f1.x, bA.z), 0.f),
                                       fmaxf(fmaf(di, f1.y, bA.w), 0.f));
        __half2 h2 = __floats2half2_rn(fmaxf(fmaf(di, f2.x, bB.x), 0.f),
                                       fmaxf(fmaf(di, f2.y, bB.y), 0.f));
        __half2 h3 = __floats2half2_rn(fmaxf(fmaf(di, f3.x, bB.z), 0.f),
                                       fmaxf(fmaf(di, f3.y, bB.w), 0.f));
        uint4 st;
        st.x = *reinterpret_cast<unsigned*>(&h0);
        st.y = *reinterpret_cast<unsigned*>(&h1);
        st.z = *reinterpret_cast<unsigned*>(&h2);
        st.w = *reinterpret_cast<unsigned*>(&h3);
        *reinterpret_cast<uint4*>(outh + (size_t)gw * HDIM + s * 8) = st;
    }
}

// ---------------- mean pool over nodes (fp16 input) ------------------------------
__global__ void k_pool(const __half2* __restrict__ h2) {
    __shared__ float2 sh[256];
    int c = threadIdx.x & 31;       // half2 column
    int seg = threadIdx.x >> 5;     // 0..7
    float2 acc = make_float2(0.f, 0.f);
    for (int r = blockIdx.x * 8 + seg; r < N_NODES; r += gridDim.x * 8) {
        float2 v = __half22float2(h2[(size_t)r * 32 + c]);
        acc.x += v.x; acc.y += v.y;
    }
    sh[threadIdx.x] = acc;
    __syncthreads();
    if (threadIdx.x < 32) {
        float2 s = sh[c];
        #pragma unroll
        for (int k = 1; k < 8; k++) {
            s.x += sh[k * 32 + c].x;
            s.y += sh[k * 32 + c].y;
        }
        atomicAdd(&g_pool[2 * c],     s.x);
        atomicAdd(&g_pool[2 * c + 1], s.y);
    }
}

// ---------------- head ------------------------------------------------------------
__global__ void k_head(const float* __restrict__ gf,
                       const float* __restrict__ w_glob, const float* __restrict__ b_glob,
                       const float* __restrict__ w_fc1, const float* __restrict__ b_fc1,
                       const float* __restrict__ w_fc2, const float* __restrict__ b_fc2,
                       float* __restrict__ out) {
    __shared__ float xc[2 * HDIM];
    __shared__ float t1[HDIM];
    int t = threadIdx.x;

    xc[t] = g_pool[t] * (1.0f / (float)N_NODES);

    float a = b_glob[t];
    #pragma unroll
    for (int k = 0; k < FGLOB; k++) a += gf[k] * w_glob[k * HDIM + t];
    xc[HDIM + t] = fmaxf(a, 0.f);
    __syncthreads();

    float u = b_fc1[t];
    #pragma unroll 8
    for (int k = 0; k < 2 * HDIM; k++) u += xc[k] * w_fc1[k * HDIM + t];
    t1[t] = fmaxf(u, 0.f);
    __syncthreads();

    float o = b_fc2[t];
    #pragma unroll 8
    for (int k = 0; k < HDIM; k++) o += t1[k] * w_fc2[k * OUTDIM + t];
    out[t] = o;
}

// ---------------- launch ------------------------------------------------------
extern "C" void kernel_launch(void* const* d_in, const int* in_sizes, int n_in,
                              void* d_out, int out_size) {
    const float* x      = (const float*)d_in[0];
    const int*   ei     = (const int*)  d_in[1];   // [2,E]: first E = src, next E = dst
    const float* gf     = (const float*)d_in[2];
    const float* w_node = (const float*)d_in[3];
    const float* b_node = (const float*)d_in[4];
    const float* w_glob = (const float*)d_in[5];
    const float* b_glob = (const float*)d_in[6];
    const float* w_c[3] = {(const float*)d_in[7], (const float*)d_in[9],  (const float*)d_in[11]};
    const float* b_c[3] = {(const float*)d_in[8], (const float*)d_in[10], (const float*)d_in[12]};
    const float* w_fc1  = (const float*)d_in[13];
    const float* b_fc1  = (const float*)d_in[14];
    const float* w_fc2  = (const float*)d_in[15];
    const float* b_fc2  = (const float*)d_in[16];
    float* out = (float*)d_out;

    __half *p_hf, *p_wh;
    unsigned int *p_hw8;
    int *p_cnt;
    cudaGetSymbolAddress((void**)&p_hf,  g_hf);
    cudaGetSymbolAddress((void**)&p_wh,  g_wh);
    cudaGetSymbolAddress((void**)&p_hw8, g_hw8);
    cudaGetSymbolAddress((void**)&p_cnt, g_cnt);

    static cudaStream_t s_side = nullptr;
    static cudaEvent_t  s_evFork = nullptr, s_evFill = nullptr;
    if (!s_side) {
        cudaStreamCreateWithFlags(&s_side, cudaStreamNonBlocking);
        cudaEventCreateWithFlags(&s_evFork, cudaEventDisableTiming);
        cudaEventCreateWithFlags(&s_evFill, cudaEventDisableTiming);
    }

    const int TB = 256;
    const int HG = (N_NODES + 127) / 128;   // 782 blocks

    // fork: CSR build on side stream (memset -> slot fill -> dis)
    cudaEventRecord(s_evFork, 0);
    cudaStreamWaitEvent(s_side, s_evFork, 0);
    cudaMemsetAsync(p_cnt, 0, N_NODES * sizeof(int), s_side);
    k_fill<<<(N_EDGES + TB - 1) / TB, TB, 0, s_side>>>(ei, ei + N_EDGES);
    k_dis <<<(N_NODES + TB - 1) / TB, TB, 0, s_side>>>();
    cudaEventRecord(s_evFill, s_side);

    // main (concurrent with CSR build): W pre-convert + layer-1 embed+transform
    // (hmma1 writes UNSCALED messages -> no graph dependence)
    k_prep<<<(3 * HDIM * HDIM + TB - 1) / TB, TB>>>(w_c[0], w_c[1], w_c[2]);
    k_hmma<true><<<HG, 256>>>(nullptr, &((__half(*)[HDIM*HDIM])p_wh)[0][0],
                              x, w_node, b_node, p_hw8);

    // join: aggregation needs CSR + dis
    cudaStreamWaitEvent(0, s_evFill, 0);
    k_agg<true><<<(N_NODES * 32 + TB - 1) / TB, TB>>>((const uint2*)p_hw8, b_c[0], p_hf);

    for (int l = 1; l < 3; l++) {
        k_hmma<false><<<HG, 256>>>(p_hf, &((__half(*)[HDIM*HDIM])p_wh)[l][0],
                                   nullptr, nullptr, nullptr, p_hw8);
        k_agg<false><<<(N_NODES * 32 + TB - 1) / TB, TB>>>((const uint2*)p_hw8, b_c[l], p_hf);
    }

    // pool + head
    k_pool<<<256, 256>>>((const __half2*)p_hf);
    k_head<<<1, 64>>>(gf, w_glob, b_glob, w_fc1, b_fc1, w_fc2, b_fc2, out);
}

// round 14
// speedup vs baseline: 1.3717x; 1.1628x over previous
#include <cuda_runtime.h>
#include <cuda_fp16.h>
#include <cuda_fp8.h>
#include <cstdint>

#define N_NODES 100000
#define N_EDGES 1600000
#define FNODE   32
#define FGLOB   16
#define HDIM    64
#define OUTDIM  64
#define MAXDEG  128    // Poisson(16) max over 100k nodes ~50; 128 is a >=8-sigma bound

#define MSG_SCALE     64.0f
#define INV_MSG_SCALE (1.0f / 64.0f)

// ---------------- scratch (device globals: no allocations allowed) ----------
__device__ int   g_cnt[N_NODES];                                 // degree; fill cursor
__device__ __align__(16) int g_csr[(size_t)N_NODES * MAXDEG];    // slot-based CSR
__device__ float g_dis[N_NODES];
__device__ __align__(16) __half g_wh[3][HDIM * HDIM];            // [0]=Wc(32x64), [1],[2]=fp16 W
__device__ float g_bc[HDIM];                                     // bc = bn @ W0
__device__ __align__(16) __half g_hf[(size_t)N_NODES * HDIM];    // node features fp16
__device__ __align__(16) unsigned int g_hw8[(size_t)N_NODES * 16]; // fp8x4 msgs, 64B/row
__device__ float g_pool[HDIM];

// ---------------- prep: Wc = Wn@W0, bc = bn@W0 (block 0); W1,W2 -> fp16 ----------
__global__ void k_prep(const float* __restrict__ w0, const float* __restrict__ w1,
                       const float* __restrict__ w2, const float* __restrict__ wn,
                       const float* __restrict__ bn) {
    if (blockIdx.x == 0) {
        __shared__ float WnS[FNODE * HDIM];
        __shared__ float W0S[HDIM * HDIM];
        int tid = threadIdx.x;
        for (int i = tid; i < FNODE * HDIM / 4; i += 256)
            reinterpret_cast<float4*>(WnS)[i] = reinterpret_cast<const float4*>(wn)[i];
        for (int i = tid; i < HDIM * HDIM / 4; i += 256)
            reinterpret_cast<float4*>(W0S)[i] = reinterpret_cast<const float4*>(w0)[i];
        __syncthreads();
        for (int idx = tid; idx < FNODE * HDIM; idx += 256) {
            int i = idx >> 6, j = idx & 63;
            float s = 0.f;
            #pragma unroll 8
            for (int k = 0; k < HDIM; k++) s += WnS[i * HDIM + k] * W0S[k * HDIM + j];
            g_wh[0][idx] = __float2half(s);
        }
        if (tid < HDIM) {
            float s = 0.f;
            #pragma unroll 8
            for (int k = 0; k < HDIM; k++) s += bn[k] * W0S[k * HDIM + tid];
            g_bc[tid] = s;
        }
    } else {
        int base = (blockIdx.x - 1) * blockDim.x + threadIdx.x;
        int stride = (gridDim.x - 1) * blockDim.x;
        for (int idx = base; idx < 2 * HDIM * HDIM; idx += stride) {
            if (idx < HDIM * HDIM) g_wh[1][idx] = __float2half(w1[idx]);
            else                   g_wh[2][idx - HDIM * HDIM] = __float2half(w2[idx - HDIM * HDIM]);
        }
    }
}

// ---------------- fused count+fill: slot-based CSR (one atomic per edge) ---------
__global__ void k_fill(const int* __restrict__ src, const int* __restrict__ dst) {
    int e = blockIdx.x * blockDim.x + threadIdx.x;
    if (e < N_EDGES) {
        int d = dst[e];
        int slot = atomicAdd(&g_cnt[d], 1);
        g_csr[(size_t)d * MAXDEG + slot] = src[e];
    }
}

// ---------------- dis = rsqrt(cnt+1) + pool zero ----------------------------------
__global__ void k_dis() {
    int i = blockIdx.x * blockDim.x + threadIdx.x;
    if (i < N_NODES) g_dis[i] = rsqrtf((float)(g_cnt[i] + 1));
    if (i < HDIM) g_pool[i] = 0.f;
}

// ---------------- fp8x2 -> half2 helpers -----------------------------------------
__device__ __forceinline__ __half2 fp8x2_to_h2(unsigned short u) {
    __half2_raw hr = __nv_cvt_fp8x2_to_halfraw2(u, __NV_E4M3);
    return *reinterpret_cast<__half2*>(&hr);
}
__device__ __forceinline__ __half2 u2h2(unsigned int u) {
    return *reinterpret_cast<__half2*>(&u);
}

#define APITCH 72      // halves; conflict-free ldmatrix (144B rows)
#define S8P    36      // ushorts per padded fp8 row (32 data + 4 pad)

// ---------------- layer-1 HMMA: msgs = fp8(64 * (x @ Wc + bc)), K=32 --------------
// UNSCALED by dis (applied per-edge in agg) -> no dependence on the graph build.
__global__ void k_hmma1(const float* __restrict__ xin, unsigned int* __restrict__ out8) {
    __shared__ __half Wsm[FNODE * APITCH];    // Wc: 32 K-rows x 64 cols
    __shared__ __half Asm[128 * APITCH];
    __shared__ float BcS[HDIM];
    int tid = threadIdx.x;
    int lane = tid & 31, wid = tid >> 5;
    int rowBase = blockIdx.x * 128;

    // stage Wc (fp16, uint4 = 8 halves; 256 uint4)
    for (int i = tid; i < FNODE * 8; i += 256) {
        int r = i >> 3, c8 = i & 7;
        *reinterpret_cast<uint4*>(&Wsm[r * APITCH + c8 * 8]) =
            *reinterpret_cast<const uint4*>(&g_wh[0][r * HDIM + c8 * 8]);
    }
    if (tid < HDIM) BcS[tid] = g_bc[tid];

    // stage A = fp16(x): 128 rows x 32 cols; 512 groups of 8 cols
    for (int i = tid; i < 128 * 4; i += 256) {
        int r = i >> 2, c8 = i & 3;
        int gr = rowBase + r;
        uint4 hv = make_uint4(0u, 0u, 0u, 0u);
        if (gr < N_NODES) {
            const float4* xr = reinterpret_cast<const float4*>(xin + (size_t)gr * FNODE + c8 * 8);
            float4 a = __ldg(&xr[0]);
            float4 b = __ldg(&xr[1]);
            __half2 h0 = __floats2half2_rn(a.x, a.y);
            __half2 h1 = __floats2half2_rn(a.z, a.w);
            __half2 h2 = __floats2half2_rn(b.x, b.y);
            __half2 h3 = __floats2half2_rn(b.z, b.w);
            hv.x = *reinterpret_cast<unsigned*>(&h0);
            hv.y = *reinterpret_cast<unsigned*>(&h1);
            hv.z = *reinterpret_cast<unsigned*>(&h2);
            hv.w = *reinterpret_cast<unsigned*>(&h3);
        }
        *reinterpret_cast<uint4*>(&Asm[r * APITCH + c8 * 8]) = hv;
    }
    __syncthreads();

    float acc[8][4];
    #pragma unroll
    for (int j = 0; j < 8; j++)
        #pragma unroll
        for (int q = 0; q < 4; q++) acc[j][q] = 0.f;

    uint32_t aAddr = (uint32_t)__cvta_generic_to_shared(
        &Asm[(wid * 16 + (lane & 15)) * APITCH + (lane >> 4) * 8]);
    uint32_t bAddr = (uint32_t)__cvta_generic_to_shared(
        &Wsm[(lane & 15) * APITCH]);

    #pragma unroll
    for (int k = 0; k < 2; k++) {             // K=32 -> 2 k-steps
        uint32_t a0, a1, a2, a3;
        asm volatile("ldmatrix.sync.aligned.m8n8.x4.shared.b16 {%0,%1,%2,%3}, [%4];\n"
                     : "=r"(a0), "=r"(a1), "=r"(a2), "=r"(a3)
                     : "r"(aAddr + k * 16 * 2));
        #pragma unroll
        for (int j = 0; j < 8; j++) {
            uint32_t b0, b1;
            asm volatile("ldmatrix.sync.aligned.m8n8.x2.trans.shared.b16 {%0,%1}, [%2];\n"
                         : "=r"(b0), "=r"(b1)
                         : "r"(bAddr + (k * 16 * APITCH + j * 8) * 2));
            asm volatile("mma.sync.aligned.m16n8k16.row.col.f32.f16.f16.f32 "
                         "{%0,%1,%2,%3}, {%4,%5,%6,%7}, {%8,%9}, {%0,%1,%2,%3};\n"
                         : "+f"(acc[j][0]), "+f"(acc[j][1]), "+f"(acc[j][2]), "+f"(acc[j][3])
                         : "r"(a0), "r"(a1), "r"(a2), "r"(a3), "r"(b0), "r"(b1));
        }
    }

    __syncthreads();
    unsigned short* S8 = reinterpret_cast<unsigned short*>(Asm);   // [128][S8P]

    int g = lane >> 2, q = lane & 3;
    int r0l = wid * 16 + g;
    int r1l = r0l + 8;
    #pragma unroll
    for (int j = 0; j < 8; j++) {
        float bcx = BcS[j * 8 + q * 2];
        float bcy = BcS[j * 8 + q * 2 + 1];
        S8[r0l * S8P + j * 4 + q] = __nv_cvt_float2_to_fp8x2(
            make_float2((acc[j][0] + bcx) * MSG_SCALE, (acc[j][1] + bcy) * MSG_SCALE),
            __NV_SATFINITE, __NV_E4M3);
        S8[r1l * S8P + j * 4 + q] = __nv_cvt_float2_to_fp8x2(
            make_float2((acc[j][2] + bcx) * MSG_SCALE, (acc[j][3] + bcy) * MSG_SCALE),
            __NV_SATFINITE, __NV_E4M3);
    }
    __syncthreads();

    for (int i = tid; i < 128 * 8; i += 256) {
        int r = i >> 3, c = i & 7;
        int grow = rowBase + r;
        if (grow < N_NODES) {
            uint2 v = *reinterpret_cast<const uint2*>(&S8[r * S8P + c * 4]);
            *reinterpret_cast<uint2*>(&out8[(size_t)grow * 16 + c * 2]) = v;
        }
    }
}

// ---------------- HMMA conv transform (layers 2,3): pre-scaled msgs ---------------
__global__ void k_hmma(const __half* __restrict__ hin, const __half* __restrict__ wh,
                       unsigned int* __restrict__ out8) {
    __shared__ __half Wsm[HDIM * APITCH];
    __shared__ __half Asm[128 * APITCH];
    int tid = threadIdx.x;
    int lane = tid & 31, wid = tid >> 5;
    int rowBase = blockIdx.x * 128;

    for (int i = tid; i < HDIM * 8; i += 256) {
        int r = i >> 3, c8 = i & 7;
        *reinterpret_cast<uint4*>(&Wsm[r * APITCH + c8 * 8]) =
            *reinterpret_cast<const uint4*>(wh + r * HDIM + c8 * 8);
    }
    for (int i = tid; i < 128 * 8; i += 256) {
        int r = i >> 3, c8 = i & 7;
        int gr = rowBase + r;
        uint4 v = make_uint4(0u, 0u, 0u, 0u);
        if (gr < N_NODES)
            v = *reinterpret_cast<const uint4*>(hin + (size_t)gr * HDIM + c8 * 8);
        *reinterpret_cast<uint4*>(&Asm[r * APITCH + c8 * 8]) = v;
    }
    __syncthreads();

    float acc[8][4];
    #pragma unroll
    for (int j = 0; j < 8; j++)
        #pragma unroll
        for (int q = 0; q < 4; q++) acc[j][q] = 0.f;

    uint32_t aAddr = (uint32_t)__cvta_generic_to_shared(
        &Asm[(wid * 16 + (lane & 15)) * APITCH + (lane >> 4) * 8]);
    uint32_t bAddr = (uint32_t)__cvta_generic_to_shared(
        &Wsm[(lane & 15) * APITCH]);

    #pragma unroll
    for (int k = 0; k < 4; k++) {
        uint32_t a0, a1, a2, a3;
        asm volatile("ldmatrix.sync.aligned.m8n8.x4.shared.b16 {%0,%1,%2,%3}, [%4];\n"
                     : "=r"(a0), "=r"(a1), "=r"(a2), "=r"(a3)
                     : "r"(aAddr + k * 16 * 2));
        #pragma unroll
        for (int j = 0; j < 8; j++) {
            uint32_t b0, b1;
            asm volatile("ldmatrix.sync.aligned.m8n8.x2.trans.shared.b16 {%0,%1}, [%2];\n"
                         : "=r"(b0), "=r"(b1)
                         : "r"(bAddr + (k * 16 * APITCH + j * 8) * 2));
            asm volatile("mma.sync.aligned.m16n8k16.row.col.f32.f16.f16.f32 "
                         "{%0,%1,%2,%3}, {%4,%5,%6,%7}, {%8,%9}, {%0,%1,%2,%3};\n"
                         : "+f"(acc[j][0]), "+f"(acc[j][1]), "+f"(acc[j][2]), "+f"(acc[j][3])
                         : "r"(a0), "r"(a1), "r"(a2), "r"(a3), "r"(b0), "r"(b1));
        }
    }

    __syncthreads();
    unsigned short* S8 = reinterpret_cast<unsigned short*>(Asm);   // [128][S8P]

    int g = lane >> 2, q = lane & 3;
    int r0l = wid * 16 + g;
    int r1l = r0l + 8;
    int gr0 = rowBase + r0l, gr1 = rowBase + r1l;
    float d0 = (gr0 < N_NODES) ? g_dis[gr0] * MSG_SCALE : 0.f;
    float d1 = (gr1 < N_NODES) ? g_dis[gr1] * MSG_SCALE : 0.f;
    #pragma unroll
    for (int j = 0; j < 8; j++) {
        S8[r0l * S8P + j * 4 + q] = __nv_cvt_float2_to_fp8x2(
            make_float2(acc[j][0] * d0, acc[j][1] * d0), __NV_SATFINITE, __NV_E4M3);
        S8[r1l * S8P + j * 4 + q] = __nv_cvt_float2_to_fp8x2(
            make_float2(acc[j][2] * d1, acc[j][3] * d1), __NV_SATFINITE, __NV_E4M3);
    }
    __syncthreads();

    for (int i = tid; i < 128 * 8; i += 256) {
        int r = i >> 3, c = i & 7;
        int grow = rowBase + r;
        if (grow < N_NODES) {
            uint2 v = *reinterpret_cast<const uint2*>(&S8[r * S8P + c * 4]);
            *reinterpret_cast<uint2*>(&out8[(size_t)grow * 16 + c * 2]) = v;
        }
    }
}

// ---------------- aggregation: warp/node, 8 lanes/row, 4 edges per LDG -----------
// EDIS=true : msgs unscaled -> per-edge dis[src] applied via hfma2 (layer 1)
// EDIS=false: msgs pre-scaled by dis[src] (layers 2,3)
template<bool EDIS>
__global__ void k_agg(const uint2* __restrict__ hw,
                      const float* __restrict__ bias, __half* __restrict__ outh) {
    int gw = (blockIdx.x * blockDim.x + threadIdx.x) >> 5;
    int lane = threadIdx.x & 31;
    if (gw >= N_NODES) return;
    int e = lane >> 3;           // edge slot 0..3
    int s = lane & 7;            // uint2 column (8 fp8 cols)

    float disg = __ldg(&g_dis[gw]);

    __half2 acc0 = __float2half2_rn(0.f), acc1 = acc0, acc2 = acc0, acc3 = acc0;

    if (e == 0) {                // self loop
        uint2 v = __ldg(&hw[(size_t)gw * 8 + s]);
        __half2 v0 = fp8x2_to_h2((unsigned short)(v.x & 0xffffu));
        __half2 v1 = fp8x2_to_h2((unsigned short)(v.x >> 16));
        __half2 v2 = fp8x2_to_h2((unsigned short)(v.y & 0xffffu));
        __half2 v3 = fp8x2_to_h2((unsigned short)(v.y >> 16));
        if (EDIS) {
            __half2 dh = __float2half2_rn(disg);
            acc0 = __hmul2(v0, dh); acc1 = __hmul2(v1, dh);
            acc2 = __hmul2(v2, dh); acc3 = __hmul2(v3, dh);
        } else {
            acc0 = v0; acc1 = v1; acc2 = v2; acc3 = v3;
        }
    }

    int cnt = g_cnt[gw];
    const int* row = g_csr + (size_t)gw * MAXDEG;
    int j = 0;
    for (; j + 4 <= cnt; j += 4) {
        int idx = __ldg(&row[j + e]);
        uint2 v = __ldg(&hw[(size_t)idx * 8 + s]);
        __half2 v0 = fp8x2_to_h2((unsigned short)(v.x & 0xffffu));
        __half2 v1 = fp8x2_to_h2((unsigned short)(v.x >> 16));
        __half2 v2 = fp8x2_to_h2((unsigned short)(v.y & 0xffffu));
        __half2 v3 = fp8x2_to_h2((unsigned short)(v.y >> 16));
        if (EDIS) {
            __half2 dh = __float2half2_rn(__ldg(&g_dis[idx]));
            acc0 = __hfma2(v0, dh, acc0); acc1 = __hfma2(v1, dh, acc1);
            acc2 = __hfma2(v2, dh, acc2); acc3 = __hfma2(v3, dh, acc3);
        } else {
            acc0 = __hadd2(acc0, v0); acc1 = __hadd2(acc1, v1);
            acc2 = __hadd2(acc2, v2); acc3 = __hadd2(acc3, v3);
        }
    }
    int rem = cnt - j;           // 0..3, warp-uniform
    if (e < rem) {
        int idx = __ldg(&row[j + e]);
        uint2 v = __ldg(&hw[(size_t)idx * 8 + s]);
        __half2 v0 = fp8x2_to_h2((unsigned short)(v.x & 0xffffu));
        __half2 v1 = fp8x2_to_h2((unsigned short)(v.x >> 16));
        __half2 v2 = fp8x2_to_h2((unsigned short)(v.y & 0xffffu));
        __half2 v3 = fp8x2_to_h2((unsigned short)(v.y >> 16));
        if (EDIS) {
            __half2 dh = __float2half2_rn(__ldg(&g_dis[idx]));
            acc0 = __hfma2(v0, dh, acc0); acc1 = __hfma2(v1, dh, acc1);
            acc2 = __hfma2(v2, dh, acc2); acc3 = __hfma2(v3, dh, acc3);
        } else {
            acc0 = __hadd2(acc0, v0); acc1 = __hadd2(acc1, v1);
            acc2 = __hadd2(acc2, v2); acc3 = __hadd2(acc3, v3);
        }
    }

    // reduce across edge slots (xor 8, then 16)
    unsigned ua0 = *reinterpret_cast<unsigned*>(&acc0);
    unsigned ua1 = *reinterpret_cast<unsigned*>(&acc1);
    unsigned ua2 = *reinterpret_cast<unsigned*>(&acc2);
    unsigned ua3 = *reinterpret_cast<unsigned*>(&acc3);
    acc0 = __hadd2(u2h2(ua0), u2h2(__shfl_xor_sync(0xffffffffu, ua0, 8)));
    acc1 = __hadd2(u2h2(ua1), u2h2(__shfl_xor_sync(0xffffffffu, ua1, 8)));
    acc2 = __hadd2(u2h2(ua2), u2h2(__shfl_xor_sync(0xffffffffu, ua2, 8)));
    acc3 = __hadd2(u2h2(ua3), u2h2(__shfl_xor_sync(0xffffffffu, ua3, 8)));
    ua0 = *reinterpret_cast<unsigned*>(&acc0);
    ua1 = *reinterpret_cast<unsigned*>(&acc1);
    ua2 = *reinterpret_cast<unsigned*>(&acc2);
    ua3 = *reinterpret_cast<unsigned*>(&acc3);
    acc0 = __hadd2(u2h2(ua0), u2h2(__shfl_xor_sync(0xffffffffu, ua0, 16)));
    acc1 = __hadd2(u2h2(ua1), u2h2(__shfl_xor_sync(0xffffffffu, ua1, 16)));
    acc2 = __hadd2(u2h2(ua2), u2h2(__shfl_xor_sync(0xffffffffu, ua2, 16)));
    acc3 = __hadd2(u2h2(ua3), u2h2(__shfl_xor_sync(0xffffffffu, ua3, 16)));

    if (e == 0) {
        float di = disg * INV_MSG_SCALE;
        float4 bA = __ldg(reinterpret_cast<const float4*>(bias) + 2 * s);
        float4 bB = __ldg(reinterpret_cast<const float4*>(bias) + 2 * s + 1);
        float2 f0 = __half22float2(acc0), f1 = __half22float2(acc1);
        float2 f2 = __half22float2(acc2), f3 = __half22float2(acc3);
        __half2 h0 = __floats2half2_rn(fmaxf(fmaf(di, f0.x, bA.x), 0.f),
                                       fmaxf(fmaf(di, f0.y, bA.y), 0.f));
        __half2 h1 = __floats2half2_rn(fmaxf(fmaf(di, f1.x, bA.z), 0.f),
                                       fmaxf(fmaf(di, f1.y, bA.w), 0.f));
        __half2 h2 = __floats2half2_rn(fmaxf(fmaf(di, f2.x, bB.x), 0.f),
                                       fmaxf(fmaf(di, f2.y, bB.y), 0.f));
        __half2 h3 = __floats2half2_rn(fmaxf(fmaf(di, f3.x, bB.z), 0.f),
                                       fmaxf(fmaf(di, f3.y, bB.w), 0.f));
        uint4 st;
        st.x = *reinterpret_cast<unsigned*>(&h0);
        st.y = *reinterpret_cast<unsigned*>(&h1);
        st.z = *reinterpret_cast<unsigned*>(&h2);
        st.w = *reinterpret_cast<unsigned*>(&h3);
        *reinterpret_cast<uint4*>(outh + (size_t)gw * HDIM + s * 8) = st;
    }
}

// ---------------- mean pool over nodes (fp16 input) ------------------------------
__global__ void k_pool(const __half2* __restrict__ h2) {
    __shared__ float2 sh[256];
    int c = threadIdx.x & 31;       // half2 column
    int seg = threadIdx.x >> 5;     // 0..7
    float2 acc = make_float2(0.f, 0.f);
    for (int r = blockIdx.x * 8 + seg; r < N_NODES; r += gridDim.x * 8) {
        float2 v = __half22float2(h2[(size_t)r * 32 + c]);
        acc.x += v.x; acc.y += v.y;
    }
    sh[threadIdx.x] = acc;
    __syncthreads();
    if (threadIdx.x < 32) {
        float2 s = sh[c];
        #pragma unroll
        for (int k = 1; k < 8; k++) {
            s.x += sh[k * 32 + c].x;
            s.y += sh[k * 32 + c].y;
        }
        atomicAdd(&g_pool[2 * c],     s.x);
        atomicAdd(&g_pool[2 * c + 1], s.y);
    }
}

// ---------------- head ------------------------------------------------------------
__global__ void k_head(const float* __restrict__ gf,
                       const float* __restrict__ w_glob, const float* __restrict__ b_glob,
                       const float* __restrict__ w_fc1, const float* __restrict__ b_fc1,
                       const float* __restrict__ w_fc2, const float* __restrict__ b_fc2,
                       float* __restrict__ out) {
    __shared__ float xc[2 * HDIM];
    __shared__ float t1[HDIM];
    int t = threadIdx.x;

    xc[t] = g_pool[t] * (1.0f / (float)N_NODES);

    float a = b_glob[t];
    #pragma unroll
    for (int k = 0; k < FGLOB; k++) a += gf[k] * w_glob[k * HDIM + t];
    xc[HDIM + t] = fmaxf(a, 0.f);
    __syncthreads();

    float u = b_fc1[t];
    #pragma unroll 8
    for (int k = 0; k < 2 * HDIM; k++) u += xc[k] * w_fc1[k * HDIM + t];
    t1[t] = fmaxf(u, 0.f);
    __syncthreads();

    float o = b_fc2[t];
    #pragma unroll 8
    for (int k = 0; k < HDIM; k++) o += t1[k] * w_fc2[k * OUTDIM + t];
    out[t] = o;
}

// ---------------- launch ------------------------------------------------------
extern "C" void kernel_launch(void* const* d_in, const int* in_sizes, int n_in,
                              void* d_out, int out_size) {
    const float* x      = (const float*)d_in[0];
    const int*   ei     = (const int*)  d_in[1];   // [2,E]: first E = src, next E = dst
    const float* gf     = (const float*)d_in[2];
    const float* w_node = (const float*)d_in[3];
    const float* b_node = (const float*)d_in[4];
    const float* w_glob = (const float*)d_in[5];
    const float* b_glob = (const float*)d_in[6];
    const float* w_c[3] = {(const float*)d_in[7], (const float*)d_in[9],  (const float*)d_in[11]};
    const float* b_c[3] = {(const float*)d_in[8], (const float*)d_in[10], (const float*)d_in[12]};
    const float* w_fc1  = (const float*)d_in[13];
    const float* b_fc1  = (const float*)d_in[14];
    const float* w_fc2  = (const float*)d_in[15];
    const float* b_fc2  = (const float*)d_in[16];
    float* out = (float*)d_out;

    __half *p_hf, *p_wh;
    unsigned int *p_hw8;
    int *p_cnt;
    cudaGetSymbolAddress((void**)&p_hf,  g_hf);
    cudaGetSymbolAddress((void**)&p_wh,  g_wh);
    cudaGetSymbolAddress((void**)&p_hw8, g_hw8);
    cudaGetSymbolAddress((void**)&p_cnt, g_cnt);

    static cudaStream_t s_side = nullptr;
    static cudaEvent_t  s_evFork = nullptr, s_evFill = nullptr;
    if (!s_side) {
        cudaStreamCreateWithFlags(&s_side, cudaStreamNonBlocking);
        cudaEventCreateWithFlags(&s_evFork, cudaEventDisableTiming);
        cudaEventCreateWithFlags(&s_evFill, cudaEventDisableTiming);
    }

    const int TB = 256;
    const int HG = (N_NODES + 127) / 128;   // 782 blocks

    // fork: CSR build on side stream (memset -> slot fill -> dis)
    cudaEventRecord(s_evFork, 0);
    cudaStreamWaitEvent(s_side, s_evFork, 0);
    cudaMemsetAsync(p_cnt, 0, N_NODES * sizeof(int), s_side);
    k_fill<<<(N_EDGES + TB - 1) / TB, TB, 0, s_side>>>(ei, ei + N_EDGES);
    k_dis <<<(N_NODES + TB - 1) / TB, TB, 0, s_side>>>();
    cudaEventRecord(s_evFill, s_side);

    // main (concurrent with CSR build): prep (Wc=Wn@W0, bc, fp16 W1/W2),
    // then layer-1 HMMA over x with combined weights (UNSCALED -> no graph dep)
    k_prep<<<9, 256>>>(w_c[0], w_c[1], w_c[2], w_node, b_node);
    k_hmma1<<<HG, 256>>>(x, p_hw8);

    // join: aggregation needs CSR + dis
    cudaStreamWaitEvent(0, s_evFill, 0);
    k_agg<true><<<(N_NODES * 32 + TB - 1) / TB, TB>>>((const uint2*)p_hw8, b_c[0], p_hf);

    for (int l = 1; l < 3; l++) {
        k_hmma<<<HG, 256>>>(p_hf, &((__half(*)[HDIM*HDIM])p_wh)[l][0], p_hw8);
        k_agg<false><<<(N_NODES * 32 + TB - 1) / TB, TB>>>((const uint2*)p_hw8, b_c[l], p_hf);
    }

    // pool + head
    k_pool<<<256, 256>>>((const __half2*)p_hf);
    k_head<<<1, 64>>>(gf, w_glob, b_glob, w_fc1, b_fc1, w_fc2, b_fc2, out);
}